// round 13
// baseline (speedup 1.0000x reference)
#include <cuda_runtime.h>
#include <cuda_fp16.h>
#include <math.h>

// Problem constants
#define NP   100000      // primal nodes
#define EPn  1600000     // primal edges
#define NDU  1600000     // dual nodes
#define EDU  3200000     // dual edges
#define EPT  (EPn + NP)  // primal edges + self loops
#define EDT  (EDU + NDU) // dual edges + self loops
#define NEG_SLOPE 0.2f
#define GRID_EDGE 444    // ~3 CTAs/SM persistent grids
#define GRID_GEMM 296

// -------- static device scratch --------
__device__ int   g_pcnt[NP], g_poff[NP], g_pfill[NP];
__device__ int   g_dcnt[NDU], g_doff[NDU], g_dfill[NDU];
__device__ int   g_psrc[EPT];
__device__ int   g_dsrc[EDT];
__device__ int   g_cursor[2];
__device__ float g_dinv[NDU];
__device__ uint2 g_xsv[NDU];        // half4: dinv[n]*dx[n][0..3]
__device__ uint4 g_hv[NP * 8];      // x @ W1, half[NP][64]
__device__ uint4 g_heluv[NP * 8];   // elu(GAT1 out), half[NP][64]
__device__ uint4 g_q1v[NDU];        // dinv[n]*relu(GCN1 out), half[NDU][8]
__device__ float g_as1[NP * 8], g_ad1[NP * 8];
__device__ float g_as2[NP], g_ad2[NP];
__device__ __half g_wth[64 * 512];  // W1 transposed fp16: [n][k]

__device__ __forceinline__ float leaky(float e) { return e > 0.f ? e : NEG_SLOPE * e; }

// ---------------- CSR (dense combined, grid-stride) ----------------
__global__ void k_hist(const int* __restrict__ ei, const int* __restrict__ dei) {
    int stride = gridDim.x * blockDim.x;
    for (int i = blockIdx.x * blockDim.x + threadIdx.x; i < EDT; i += stride) {
        if (i < EPT) {
            int dst = (i < EPn) ? ei[EPn + i] : (i - EPn);
            atomicAdd(&g_pcnt[dst], 1);
        }
        int dst = (i < EDU) ? dei[EDU + i] : (i - EDU);
        atomicAdd(&g_dcnt[dst], 1);
    }
}

__device__ __forceinline__ void alloc_chunk(const int* __restrict__ cnt,
                                            int* __restrict__ off,
                                            int* __restrict__ fill,
                                            int n, int curIdx, int doDinv, int bid,
                                            const float* __restrict__ dx,
                                            int* sh, int* basep) {
    int t = threadIdx.x;
    int i = bid * 1024 + t;
    int v = (i < n) ? cnt[i] : 0;
    sh[t] = v;
    __syncthreads();
    #pragma unroll
    for (int d = 1; d < 1024; d <<= 1) {
        int add = (t >= d) ? sh[t - d] : 0;
        __syncthreads();
        sh[t] += add;
        __syncthreads();
    }
    if (t == 1023) *basep = atomicAdd(&g_cursor[curIdx], sh[1023]);
    __syncthreads();
    if (i < n) {
        int o = *basep + sh[t] - v;   // exclusive
        off[i] = o;
        fill[i] = o;
        if (doDinv) {
            float di = rsqrtf((float)(v > 0 ? v : 1));
            g_dinv[i] = di;
            float4 xv = *(const float4*)&dx[(size_t)i * 4];
            __half2 a = __floats2half2_rn(di * xv.x, di * xv.y);
            __half2 b = __floats2half2_rn(di * xv.z, di * xv.w);
            g_xsv[i] = make_uint2(*(unsigned*)&a, *(unsigned*)&b);
        }
    }
    __syncthreads();   // smem reuse barrier
}
#define NPB 98     // ceil(NP/1024)
#define NDB 1563   // ceil(NDU/1024)
__global__ void k_alloc(const float* __restrict__ dx) {
    __shared__ int sh[1024];
    __shared__ int base;
    for (int b = blockIdx.x; b < NPB + NDB; b += gridDim.x) {
        if (b < NPB) alloc_chunk(g_pcnt, g_poff, g_pfill, NP, 0, 0, b, dx, sh, &base);
        else         alloc_chunk(g_dcnt, g_doff, g_dfill, NDU, 1, 1, b - NPB, dx, sh, &base);
    }
}

__global__ void k_fill(const int* __restrict__ ei, const int* __restrict__ dei) {
    int stride = gridDim.x * blockDim.x;
    for (int i = blockIdx.x * blockDim.x + threadIdx.x; i < EDT; i += stride) {
        if (i < EPT) {
            int src, dst;
            if (i < EPn) { src = ei[i]; dst = ei[EPn + i]; }
            else         { src = dst = i - EPn; }
            int pos = atomicAdd(&g_pfill[dst], 1);
            g_psrc[pos] = src;
        }
        int src, dst;
        if (i < EDU) { src = dei[i]; dst = dei[EDU + i]; }
        else         { src = dst = i - EDU; }
        int pos = atomicAdd(&g_dfill[dst], 1);
        g_dsrc[pos] = src;
    }
}

// ---------------- dual GCN layer 1 (grid-stride) ----------------
__global__ void k_gcn1(const float* __restrict__ Wg1, const float* __restrict__ bg1) {
    int stride = gridDim.x * blockDim.x;
    for (int n = blockIdx.x * blockDim.x + threadIdx.x; n < NDU; n += stride) {
        int s = g_doff[n], cnt = g_dcnt[n];
        float4 acc = make_float4(0.f, 0.f, 0.f, 0.f);
        int e = s + cnt;
        for (int j = s; j < e; j++) {
            int src = g_dsrc[j];
            uint2 r = g_xsv[src];
            float2 f0 = __half22float2(*(__half2*)&r.x);
            float2 f1 = __half22float2(*(__half2*)&r.y);
            acc.x += f0.x; acc.y += f0.y; acc.z += f1.x; acc.w += f1.y;
        }
        float di = g_dinv[n];
        acc.x *= di; acc.y *= di; acc.z *= di; acc.w *= di;
        float o[8];
        #pragma unroll
        for (int j = 0; j < 8; j++) {
            float v = __ldg(&bg1[j]);
            v = fmaf(acc.x, __ldg(&Wg1[0 * 8 + j]), v);
            v = fmaf(acc.y, __ldg(&Wg1[1 * 8 + j]), v);
            v = fmaf(acc.z, __ldg(&Wg1[2 * 8 + j]), v);
            v = fmaf(acc.w, __ldg(&Wg1[3 * 8 + j]), v);
            v = v > 0.f ? v : 0.f;     // ReLU
            o[j] = v * di;             // fold dinv[n] for layer 2
        }
        __half2 p0 = __floats2half2_rn(o[0], o[1]);
        __half2 p1 = __floats2half2_rn(o[2], o[3]);
        __half2 p2 = __floats2half2_rn(o[4], o[5]);
        __half2 p3 = __floats2half2_rn(o[6], o[7]);
        uint4 pk;
        pk.x = *(unsigned*)&p0; pk.y = *(unsigned*)&p1;
        pk.z = *(unsigned*)&p2; pk.w = *(unsigned*)&p3;
        g_q1v[n] = pk;
    }
}

// ---------------- dual GCN layer 2 (grid-stride) ----------------
__global__ void k_gcn2(const float* __restrict__ Wg2, const float* __restrict__ bg2,
                       float* __restrict__ qout) {
    int stride = gridDim.x * blockDim.x;
    for (int n = blockIdx.x * blockDim.x + threadIdx.x; n < NDU; n += stride) {
        int s = g_doff[n], cnt = g_dcnt[n];
        float acc[8] = {};
        int e = s + cnt;
        for (int j = s; j < e; j++) {
            int src = g_dsrc[j];
            uint4 raw = g_q1v[src];
            float2 f0 = __half22float2(*(__half2*)&raw.x);
            float2 f1 = __half22float2(*(__half2*)&raw.y);
            float2 f2 = __half22float2(*(__half2*)&raw.z);
            float2 f3 = __half22float2(*(__half2*)&raw.w);
            acc[0] += f0.x; acc[1] += f0.y;
            acc[2] += f1.x; acc[3] += f1.y;
            acc[4] += f2.x; acc[5] += f2.y;
            acc[6] += f3.x; acc[7] += f3.y;
        }
        float di = g_dinv[n];
        #pragma unroll
        for (int i = 0; i < 8; i++) acc[i] *= di;
        #pragma unroll
        for (int j4 = 0; j4 < 4; j4++) {
            float4 ov;
            float* op = (float*)&ov;
            #pragma unroll
            for (int t = 0; t < 4; t++) {
                int j = j4 * 4 + t;
                float v = __ldg(&bg2[j]);
                #pragma unroll
                for (int i = 0; i < 8; i++) v = fmaf(acc[i], __ldg(&Wg2[i * 16 + j]), v);
                op[t] = v;
            }
            *(float4*)&qout[(size_t)n * 16 + j4 * 4] = ov;
        }
    }
}

// ---------------- W1 -> fp16 transposed [n][k] ----------------
__global__ void k_wconv(const float* __restrict__ W1) {
    int i = blockIdx.x * 256 + threadIdx.x;
    if (i < 64 * 512) {
        int n = i >> 9, k = i & 511;
        g_wth[i] = __float2half(W1[k * 64 + n]);
    }
}

// ---------------- GEMM (fp16 TC, double-buffered, grid-stride over row tiles) ----------------
#define GBM 128
#define NTILE ((NP + GBM - 1) / GBM)
__global__ __launch_bounds__(256, 2) void k_gemm1(const float* __restrict__ x,
                                                  const float* __restrict__ att_s,
                                                  const float* __restrict__ att_d) {
    __shared__ __half Xh[2][GBM][40];
    __shared__ __half Wts[2][64][40];
    int tid = threadIdx.x;
    int lane = tid & 31;
    int w = tid >> 5;
    int la3 = lane & 3, l4 = lane >> 2;
    float ats[16], atd[16];
    #pragma unroll
    for (int n = 0; n < 8; n++) {
        int col = n * 8 + la3 * 2;
        ats[n * 2]     = __ldg(&att_s[col]);
        ats[n * 2 + 1] = __ldg(&att_s[col + 1]);
        atd[n * 2]     = __ldg(&att_d[col]);
        atd[n * 2 + 1] = __ldg(&att_d[col + 1]);
    }

    for (int tile = blockIdx.x; tile < NTILE; tile += gridDim.x) {
        int row0 = tile * GBM;
        float acc[8][4] = {};
        uint2 xs[4]; uint4 wvr;
        // preload tile 0
        #pragma unroll
        for (int i = 0; i < 4; i++) {
            int f = tid + i * 256;
            int r = f >> 3, c4 = (f & 7) << 2;
            float4 v = make_float4(0.f, 0.f, 0.f, 0.f);
            if (row0 + r < NP) v = *(const float4*)&x[(size_t)(row0 + r) * 512 + c4];
            __half2 h0 = __floats2half2_rn(v.x, v.y);
            __half2 h1 = __floats2half2_rn(v.z, v.w);
            xs[i] = make_uint2(*(unsigned*)&h0, *(unsigned*)&h1);
        }
        { int n = tid >> 2, kc = (tid & 3) * 8; wvr = *(const uint4*)&g_wth[n * 512 + kc]; }
        #pragma unroll
        for (int i = 0; i < 4; i++) {
            int f = tid + i * 256;
            int r = f >> 3, c4 = (f & 7) << 2;
            *(uint2*)&Xh[0][r][c4] = xs[i];
        }
        { int n = tid >> 2, kc = (tid & 3) * 8;
          *(uint2*)&Wts[0][n][kc]     = make_uint2(wvr.x, wvr.y);
          *(uint2*)&Wts[0][n][kc + 4] = make_uint2(wvr.z, wvr.w); }
        __syncthreads();

        for (int kt = 0; kt < 16; kt++) {
            int buf = kt & 1;
            if (kt < 15) {
                int k0 = (kt + 1) * 32;
                #pragma unroll
                for (int i = 0; i < 4; i++) {
                    int f = tid + i * 256;
                    int r = f >> 3, c4 = (f & 7) << 2;
                    float4 v = make_float4(0.f, 0.f, 0.f, 0.f);
                    if (row0 + r < NP) v = *(const float4*)&x[(size_t)(row0 + r) * 512 + k0 + c4];
                    __half2 h0 = __floats2half2_rn(v.x, v.y);
                    __half2 h1 = __floats2half2_rn(v.z, v.w);
                    xs[i] = make_uint2(*(unsigned*)&h0, *(unsigned*)&h1);
                }
                int n = tid >> 2, kc = (tid & 3) * 8;
                wvr = *(const uint4*)&g_wth[n * 512 + k0 + kc];
            }
            #pragma unroll
            for (int ks = 0; ks < 2; ks++) {
                int kk = ks * 16 + la3 * 2;
                unsigned a[4], bfr[8][2];
                int r = w * 16 + l4;
                a[0] = *(unsigned*)&Xh[buf][r][kk];
                a[1] = *(unsigned*)&Xh[buf][r + 8][kk];
                a[2] = *(unsigned*)&Xh[buf][r][kk + 8];
                a[3] = *(unsigned*)&Xh[buf][r + 8][kk + 8];
                #pragma unroll
                for (int n = 0; n < 8; n++) {
                    int nn = n * 8 + l4;
                    bfr[n][0] = *(unsigned*)&Wts[buf][nn][kk];
                    bfr[n][1] = *(unsigned*)&Wts[buf][nn][kk + 8];
                }
                #pragma unroll
                for (int n = 0; n < 8; n++)
                    asm volatile(
                        "mma.sync.aligned.m16n8k16.row.col.f32.f16.f16.f32 "
                        "{%0,%1,%2,%3}, {%4,%5,%6,%7}, {%8,%9}, {%0,%1,%2,%3};\n"
                        : "+f"(acc[n][0]), "+f"(acc[n][1]),
                          "+f"(acc[n][2]), "+f"(acc[n][3])
                        : "r"(a[0]), "r"(a[1]), "r"(a[2]), "r"(a[3]),
                          "r"(bfr[n][0]), "r"(bfr[n][1]));
            }
            if (kt < 15) {
                int ob = buf ^ 1;
                #pragma unroll
                for (int i = 0; i < 4; i++) {
                    int f = tid + i * 256;
                    int r = f >> 3, c4 = (f & 7) << 2;
                    *(uint2*)&Xh[ob][r][c4] = xs[i];
                }
                int n = tid >> 2, kc = (tid & 3) * 8;
                *(uint2*)&Wts[ob][n][kc]     = make_uint2(wvr.x, wvr.y);
                *(uint2*)&Wts[ob][n][kc + 4] = make_uint2(wvr.z, wvr.w);
                __syncthreads();
            }
        }
        // epilogue
        __half* hbase = (__half*)g_hv;
        #pragma unroll
        for (int rh = 0; rh < 2; rh++) {
            int row = row0 + w * 16 + rh * 8 + l4;
            bool ok = (row < NP);
            #pragma unroll
            for (int n = 0; n < 8; n++) {
                float c0 = acc[n][rh * 2 + 0];
                float c1 = acc[n][rh * 2 + 1];
                if (ok) {
                    __half2 hp = __floats2half2_rn(c0, c1);
                    *(__half2*)&hbase[(size_t)row * 64 + n * 8 + la3 * 2] = hp;
                }
                float ss = c0 * ats[n * 2] + c1 * ats[n * 2 + 1];
                float dd = c0 * atd[n * 2] + c1 * atd[n * 2 + 1];
                ss += __shfl_xor_sync(0xffffffffu, ss, 1);
                ss += __shfl_xor_sync(0xffffffffu, ss, 2);
                dd += __shfl_xor_sync(0xffffffffu, dd, 1);
                dd += __shfl_xor_sync(0xffffffffu, dd, 2);
                if (ok && la3 == 0) {
                    g_as1[(size_t)row * 8 + n] = ss;
                    g_ad1[(size_t)row * 8 + n] = dd;
                }
            }
        }
        __syncthreads();   // smem reuse barrier before next tile's preload
    }
}

// ---------------- GAT layer 1: half-warp per edge, grid-stride over dst ----------------
__global__ __launch_bounds__(256) void k_gat1(const float* __restrict__ b1,
                                              const float* __restrict__ W2,
                                              const float* __restrict__ as2att,
                                              const float* __restrict__ ad2att) {
    __shared__ float vs[64], vd[64];
    if (threadIdx.x < 64) {
        int c = threadIdx.x;
        float s = 0.f, d = 0.f;
        #pragma unroll
        for (int j = 0; j < 16; j++) {
            float wv = __ldg(&W2[c * 16 + j]);
            s = fmaf(wv, __ldg(&as2att[j]), s);
            d = fmaf(wv, __ldg(&ad2att[j]), d);
        }
        vs[c] = s; vd[c] = d;
    }
    __syncthreads();
    int lane = threadIdx.x & 31;
    int half = lane >> 4, hl = lane & 15;
    int c0 = hl * 4;
    int head = hl >> 1;
    int wstride = gridDim.x * (blockDim.x >> 5);
    const uint2* hb2 = (const uint2*)g_hv;
    for (int dst = (blockIdx.x * blockDim.x + threadIdx.x) >> 5; dst < NP; dst += wstride) {
        int s = g_poff[dst], cnt = g_pcnt[dst];
        const int* bp = &g_psrc[s];
        float adv = g_ad1[dst * 8 + head];
        float den = 0.f, a0 = 0.f, a1 = 0.f, a2 = 0.f, a3 = 0.f;
        int j = 0;
        for (; j + 3 < cnt; j += 4) {
            int s0 = bp[j + half], s1 = bp[j + 2 + half];
            float x0 = g_as1[s0 * 8 + head];
            float x1 = g_as1[s1 * 8 + head];
            uint2 r0 = hb2[(size_t)s0 * 16 + hl];
            uint2 r1 = hb2[(size_t)s1 * 16 + hl];
            float w0 = __expf(leaky(x0 + adv));
            float w1 = __expf(leaky(x1 + adv));
            float2 f00 = __half22float2(*(__half2*)&r0.x);
            float2 f01 = __half22float2(*(__half2*)&r0.y);
            float2 f10 = __half22float2(*(__half2*)&r1.x);
            float2 f11 = __half22float2(*(__half2*)&r1.y);
            den += w0 + w1;
            a0 = fmaf(w0, f00.x, a0); a1 = fmaf(w0, f00.y, a1);
            a2 = fmaf(w0, f01.x, a2); a3 = fmaf(w0, f01.y, a3);
            a0 = fmaf(w1, f10.x, a0); a1 = fmaf(w1, f10.y, a1);
            a2 = fmaf(w1, f11.x, a2); a3 = fmaf(w1, f11.y, a3);
        }
        for (; j < cnt; j += 2) {
            int e = j + half;
            if (e < cnt) {
                int s0 = bp[e];
                float x0 = g_as1[s0 * 8 + head];
                uint2 r0 = hb2[(size_t)s0 * 16 + hl];
                float w0 = __expf(leaky(x0 + adv));
                float2 f00 = __half22float2(*(__half2*)&r0.x);
                float2 f01 = __half22float2(*(__half2*)&r0.y);
                den += w0;
                a0 = fmaf(w0, f00.x, a0); a1 = fmaf(w0, f00.y, a1);
                a2 = fmaf(w0, f01.x, a2); a3 = fmaf(w0, f01.y, a3);
            }
        }
        a0 += __shfl_xor_sync(0xffffffffu, a0, 16);
        a1 += __shfl_xor_sync(0xffffffffu, a1, 16);
        a2 += __shfl_xor_sync(0xffffffffu, a2, 16);
        a3 += __shfl_xor_sync(0xffffffffu, a3, 16);
        den += __shfl_xor_sync(0xffffffffu, den, 16);
        float inv = 1.0f / (den + 1e-16f);
        float4 bv = *(const float4*)&b1[c0];
        a0 = a0 * inv + bv.x; a1 = a1 * inv + bv.y;
        a2 = a2 * inv + bv.z; a3 = a3 * inv + bv.w;
        a0 = a0 > 0.f ? a0 : (__expf(a0) - 1.f);   // ELU
        a1 = a1 > 0.f ? a1 : (__expf(a1) - 1.f);
        a2 = a2 > 0.f ? a2 : (__expf(a2) - 1.f);
        a3 = a3 > 0.f ? a3 : (__expf(a3) - 1.f);
        if (lane < 16) {
            __half2 h01 = __floats2half2_rn(a0, a1);
            __half2 h23 = __floats2half2_rn(a2, a3);
            ((uint2*)g_heluv)[(size_t)dst * 16 + hl] =
                make_uint2(*(unsigned*)&h01, *(unsigned*)&h23);
        }
        float ss = a0 * vs[c0] + a1 * vs[c0 + 1] + a2 * vs[c0 + 2] + a3 * vs[c0 + 3];
        float dd = a0 * vd[c0] + a1 * vd[c0 + 1] + a2 * vd[c0 + 2] + a3 * vd[c0 + 3];
        #pragma unroll
        for (int o = 8; o > 0; o >>= 1) {
            ss += __shfl_xor_sync(0xffffffffu, ss, o);
            dd += __shfl_xor_sync(0xffffffffu, dd, o);
        }
        if (lane == 0) { g_as2[dst] = ss; g_ad2[dst] = dd; }
    }
}

// ---------------- GAT layer 2: half-warp per edge, grid-stride over dst ----------------
__global__ __launch_bounds__(256) void k_gat2(const float* __restrict__ W2,
                                              const float* __restrict__ b2,
                                              float* __restrict__ out) {
    __shared__ float W2s[64 * 16];
    __shared__ float accs[8][64];
    for (int i = threadIdx.x; i < 64 * 16; i += blockDim.x) W2s[i] = W2[i];
    __syncthreads();
    int lane = threadIdx.x & 31;
    int wip = (threadIdx.x >> 5);
    int half = lane >> 4, hl = lane & 15;
    int c0 = hl * 4;
    int wstride = gridDim.x * (blockDim.x >> 5);
    const uint2* hb2 = (const uint2*)g_heluv;
    for (int dst = (blockIdx.x * blockDim.x + threadIdx.x) >> 5; dst < NP; dst += wstride) {
        int s = g_poff[dst], cnt = g_pcnt[dst];
        const int* bp = &g_psrc[s];
        float adv = g_ad2[dst];
        float den = 0.f, a0 = 0.f, a1 = 0.f, a2 = 0.f, a3 = 0.f;
        int j = 0;
        for (; j + 3 < cnt; j += 4) {
            int s0 = bp[j + half], s1 = bp[j + 2 + half];
            float x0 = g_as2[s0], x1 = g_as2[s1];
            uint2 r0 = hb2[(size_t)s0 * 16 + hl];
            uint2 r1 = hb2[(size_t)s1 * 16 + hl];
            float w0 = __expf(leaky(x0 + adv));
            float w1 = __expf(leaky(x1 + adv));
            float2 f00 = __half22float2(*(__half2*)&r0.x);
            float2 f01 = __half22float2(*(__half2*)&r0.y);
            float2 f10 = __half22float2(*(__half2*)&r1.x);
            float2 f11 = __half22float2(*(__half2*)&r1.y);
            den += w0 + w1;
            a0 = fmaf(w0, f00.x, a0); a1 = fmaf(w0, f00.y, a1);
            a2 = fmaf(w0, f01.x, a2); a3 = fmaf(w0, f01.y, a3);
            a0 = fmaf(w1, f10.x, a0); a1 = fmaf(w1, f10.y, a1);
            a2 = fmaf(w1, f11.x, a2); a3 = fmaf(w1, f11.y, a3);
        }
        for (; j < cnt; j += 2) {
            int e = j + half;
            if (e < cnt) {
                int s0 = bp[e];
                float x0 = g_as2[s0];
                uint2 r0 = hb2[(size_t)s0 * 16 + hl];
                float w0 = __expf(leaky(x0 + adv));
                float2 f00 = __half22float2(*(__half2*)&r0.x);
                float2 f01 = __half22float2(*(__half2*)&r0.y);
                den += w0;
                a0 = fmaf(w0, f00.x, a0); a1 = fmaf(w0, f00.y, a1);
                a2 = fmaf(w0, f01.x, a2); a3 = fmaf(w0, f01.y, a3);
            }
        }
        a0 += __shfl_xor_sync(0xffffffffu, a0, 16);
        a1 += __shfl_xor_sync(0xffffffffu, a1, 16);
        a2 += __shfl_xor_sync(0xffffffffu, a2, 16);
        a3 += __shfl_xor_sync(0xffffffffu, a3, 16);
        den += __shfl_xor_sync(0xffffffffu, den, 16);
        float inv = 1.0f / (den + 1e-16f);
        if (lane < 16) {
            accs[wip][c0]     = a0 * inv;
            accs[wip][c0 + 1] = a1 * inv;
            accs[wip][c0 + 2] = a2 * inv;
            accs[wip][c0 + 3] = a3 * inv;
        }
        __syncwarp();
        if (lane < 16) {
            float o = __ldg(&b2[lane]);
            #pragma unroll
            for (int c = 0; c < 64; c++) o = fmaf(accs[wip][c], W2s[c * 16 + lane], o);
            out[dst * 16 + lane] = o;
        }
        __syncwarp();
    }
}

// ---------------- launcher: forked-stream graph, persistent grids ----------------
extern "C" void kernel_launch(void* const* d_in, const int* in_sizes, int n_in,
                              void* d_out, int out_size) {
    const float* x    = (const float*)d_in[0];
    const int*   ei   = (const int*)d_in[1];
    const float* dx   = (const float*)d_in[2];
    const int*   dei  = (const int*)d_in[3];
    const float* W1   = (const float*)d_in[4];
    const float* as1a = (const float*)d_in[5];
    const float* ad1a = (const float*)d_in[6];
    const float* b1   = (const float*)d_in[7];
    const float* W2   = (const float*)d_in[8];
    const float* as2a = (const float*)d_in[9];
    const float* ad2a = (const float*)d_in[10];
    const float* b2   = (const float*)d_in[11];
    const float* Wg1  = (const float*)d_in[12];
    const float* bg1  = (const float*)d_in[13];
    const float* Wg2  = (const float*)d_in[14];
    const float* bg2  = (const float*)d_in[15];
    float* out = (float*)d_out;              // [NP,16] then [NDU,16]
    float* qout = out + (size_t)NP * 16;

    static cudaStream_t s1 = nullptr;
    static cudaEvent_t ev_fork = nullptr, ev_fill = nullptr, ev_done = nullptr;
    static void *p_pcnt = nullptr, *p_dcnt = nullptr, *p_cur = nullptr;
    if (!s1) {
        cudaStreamCreateWithFlags(&s1, cudaStreamNonBlocking);
        cudaEventCreateWithFlags(&ev_fork, cudaEventDisableTiming);
        cudaEventCreateWithFlags(&ev_fill, cudaEventDisableTiming);
        cudaEventCreateWithFlags(&ev_done, cudaEventDisableTiming);
        cudaGetSymbolAddress(&p_pcnt, g_pcnt);
        cudaGetSymbolAddress(&p_dcnt, g_dcnt);
        cudaGetSymbolAddress(&p_cur, g_cursor);
    }

    // zero counters via memset nodes
    cudaMemsetAsync(p_pcnt, 0, NP * sizeof(int), 0);
    cudaMemsetAsync(p_dcnt, 0, NDU * sizeof(int), 0);
    cudaMemsetAsync(p_cur, 0, 2 * sizeof(int), 0);

    cudaEventRecord(ev_fork, 0);
    cudaStreamWaitEvent(s1, ev_fork, 0);

    // stream 0: CSR build; s1: W-convert + GEMM (co-resident via bounded grids)
    k_hist<<<GRID_EDGE, 256>>>(ei, dei);                                    // k0
    k_wconv<<<128, 256, 0, s1>>>(W1);                                       // k1
    k_alloc<<<148, 1024>>>(dx);                                             // k2
    k_gemm1<<<GRID_GEMM, 256, 0, s1>>>(x, as1a, ad1a);                      // k3 <- profiled
    k_fill<<<GRID_EDGE, 256>>>(ei, dei);                                    // k4
    cudaEventRecord(ev_fill, 0);

    // s1: GAT branch (co-resident with GCN on stream 0)
    cudaStreamWaitEvent(s1, ev_fill, 0);
    k_gat1<<<GRID_EDGE, 256, 0, s1>>>(b1, W2, as2a, ad2a);                  // k5
    k_gat2<<<GRID_EDGE, 256, 0, s1>>>(W2, b2, out);                         // k6

    // stream 0: dual GCN
    k_gcn1<<<GRID_EDGE, 256>>>(Wg1, bg1);                                   // k7
    k_gcn2<<<GRID_EDGE, 256>>>(Wg2, bg2, qout);                             // k8

    cudaEventRecord(ev_done, s1);
    cudaStreamWaitEvent(0, ev_done, 0);
}

// round 14
// speedup vs baseline: 1.3300x; 1.3300x over previous
#include <cuda_runtime.h>
#include <cuda_fp16.h>
#include <math.h>

// Problem constants
#define NP   100000      // primal nodes
#define EPn  1600000     // primal edges
#define NDU  1600000     // dual nodes
#define EDU  3200000     // dual edges
#define EPT  (EPn + NP)  // primal edges + self loops
#define EDT  (EDU + NDU) // dual edges + self loops
#define NEG_SLOPE 0.2f

// -------- static device scratch --------
__device__ int   g_pcnt[NP], g_poff[NP], g_pfill[NP];
__device__ int   g_dcnt[NDU], g_doff[NDU], g_dfill[NDU];
__device__ int   g_psrc[EPT];
__device__ int   g_dsrc[EDT];
__device__ int   g_cursor[2];
__device__ float g_dinv[NDU];
__device__ uint2 g_xsv[NDU];        // half4: dinv[n]*dx[n][0..3]
__device__ uint4 g_hv[NP * 8];      // x @ W1, half[NP][64]
__device__ uint4 g_heluv[NP * 8];   // elu(GAT1 out), half[NP][64]
__device__ uint4 g_q1v[NDU];        // dinv[n]*relu(GCN1 out), half[NDU][8]
__device__ float g_as1[NP * 8], g_ad1[NP * 8];
__device__ float g_as2[NP], g_ad2[NP];
__device__ __half g_wth[64 * 512];  // W1 transposed fp16: [n][k]

__device__ __forceinline__ float leaky(float e) { return e > 0.f ? e : NEG_SLOPE * e; }

// ---------------- CSR (dense combined — proven R11) ----------------
__global__ void k_hist(const int* __restrict__ ei, const int* __restrict__ dei) {
    int i = blockIdx.x * blockDim.x + threadIdx.x;
    if (i < EPT) {
        int dst = (i < EPn) ? ei[EPn + i] : (i - EPn);
        atomicAdd(&g_pcnt[dst], 1);
    }
    if (i < EDT) {
        int dst = (i < EDU) ? dei[EDU + i] : (i - EDU);
        atomicAdd(&g_dcnt[dst], 1);
    }
}

__device__ __forceinline__ void alloc_body(const int* __restrict__ cnt,
                                           int* __restrict__ off,
                                           int* __restrict__ fill,
                                           int n, int curIdx, int doDinv, int bid,
                                           const float* __restrict__ dx) {
    __shared__ int sh[1024];
    __shared__ int base;
    int t = threadIdx.x;
    int i = bid * 1024 + t;
    int v = (i < n) ? cnt[i] : 0;
    sh[t] = v;
    __syncthreads();
    #pragma unroll
    for (int d = 1; d < 1024; d <<= 1) {
        int add = (t >= d) ? sh[t - d] : 0;
        __syncthreads();
        sh[t] += add;
        __syncthreads();
    }
    if (t == 1023) base = atomicAdd(&g_cursor[curIdx], sh[1023]);
    __syncthreads();
    if (i < n) {
        int o = base + sh[t] - v;   // exclusive
        off[i] = o;
        fill[i] = o;
        if (doDinv) {
            float di = rsqrtf((float)(v > 0 ? v : 1));
            g_dinv[i] = di;
            float4 xv = *(const float4*)&dx[(size_t)i * 4];
            __half2 a = __floats2half2_rn(di * xv.x, di * xv.y);
            __half2 b = __floats2half2_rn(di * xv.z, di * xv.w);
            g_xsv[i] = make_uint2(*(unsigned*)&a, *(unsigned*)&b);
        }
    }
}
#define NPB 98     // ceil(NP/1024)
#define NDB 1563   // ceil(NDU/1024)
__global__ void k_alloc(const float* __restrict__ dx) {
    if (blockIdx.x < NPB) alloc_body(g_pcnt, g_poff, g_pfill, NP, 0, 0, blockIdx.x, dx);
    else                  alloc_body(g_dcnt, g_doff, g_dfill, NDU, 1, 1, blockIdx.x - NPB, dx);
}

__global__ void k_fill(const int* __restrict__ ei, const int* __restrict__ dei) {
    int i = blockIdx.x * blockDim.x + threadIdx.x;
    if (i < EPT) {
        int src, dst;
        if (i < EPn) { src = ei[i]; dst = ei[EPn + i]; }
        else         { src = dst = i - EPn; }
        int pos = atomicAdd(&g_pfill[dst], 1);
        g_psrc[pos] = src;
    }
    if (i < EDT) {
        int src, dst;
        if (i < EDU) { src = dei[i]; dst = dei[EDU + i]; }
        else         { src = dst = i - EDU; }
        int pos = atomicAdd(&g_dfill[dst], 1);
        g_dsrc[pos] = src;
    }
}

// ---------------- dual GCN layer 1 ----------------
__global__ void k_gcn1(const float* __restrict__ Wg1, const float* __restrict__ bg1) {
    int n = blockIdx.x * blockDim.x + threadIdx.x;
    if (n >= NDU) return;
    int s = g_doff[n], cnt = g_dcnt[n];
    float4 acc = make_float4(0.f, 0.f, 0.f, 0.f);
    int e = s + cnt;
    for (int j = s; j < e; j++) {
        int src = g_dsrc[j];
        uint2 r = g_xsv[src];
        float2 f0 = __half22float2(*(__half2*)&r.x);
        float2 f1 = __half22float2(*(__half2*)&r.y);
        acc.x += f0.x; acc.y += f0.y; acc.z += f1.x; acc.w += f1.y;
    }
    float di = g_dinv[n];
    acc.x *= di; acc.y *= di; acc.z *= di; acc.w *= di;
    float o[8];
    #pragma unroll
    for (int j = 0; j < 8; j++) {
        float v = __ldg(&bg1[j]);
        v = fmaf(acc.x, __ldg(&Wg1[0 * 8 + j]), v);
        v = fmaf(acc.y, __ldg(&Wg1[1 * 8 + j]), v);
        v = fmaf(acc.z, __ldg(&Wg1[2 * 8 + j]), v);
        v = fmaf(acc.w, __ldg(&Wg1[3 * 8 + j]), v);
        v = v > 0.f ? v : 0.f;     // ReLU
        o[j] = v * di;             // fold dinv[n] for layer 2
    }
    __half2 p0 = __floats2half2_rn(o[0], o[1]);
    __half2 p1 = __floats2half2_rn(o[2], o[3]);
    __half2 p2 = __floats2half2_rn(o[4], o[5]);
    __half2 p3 = __floats2half2_rn(o[6], o[7]);
    uint4 pk;
    pk.x = *(unsigned*)&p0; pk.y = *(unsigned*)&p1;
    pk.z = *(unsigned*)&p2; pk.w = *(unsigned*)&p3;
    g_q1v[n] = pk;
}

// ---------------- dual GCN layer 2 ----------------
__global__ void k_gcn2(const float* __restrict__ Wg2, const float* __restrict__ bg2,
                       float* __restrict__ qout) {
    int n = blockIdx.x * blockDim.x + threadIdx.x;
    if (n >= NDU) return;
    int s = g_doff[n], cnt = g_dcnt[n];
    float acc[8] = {};
    int e = s + cnt;
    for (int j = s; j < e; j++) {
        int src = g_dsrc[j];
        uint4 raw = g_q1v[src];
        float2 f0 = __half22float2(*(__half2*)&raw.x);
        float2 f1 = __half22float2(*(__half2*)&raw.y);
        float2 f2 = __half22float2(*(__half2*)&raw.z);
        float2 f3 = __half22float2(*(__half2*)&raw.w);
        acc[0] += f0.x; acc[1] += f0.y;
        acc[2] += f1.x; acc[3] += f1.y;
        acc[4] += f2.x; acc[5] += f2.y;
        acc[6] += f3.x; acc[7] += f3.y;
    }
    float di = g_dinv[n];
    #pragma unroll
    for (int i = 0; i < 8; i++) acc[i] *= di;
    #pragma unroll
    for (int j4 = 0; j4 < 4; j4++) {
        float4 ov;
        float* op = (float*)&ov;
        #pragma unroll
        for (int t = 0; t < 4; t++) {
            int j = j4 * 4 + t;
            float v = __ldg(&bg2[j]);
            #pragma unroll
            for (int i = 0; i < 8; i++) v = fmaf(acc[i], __ldg(&Wg2[i * 16 + j]), v);
            op[t] = v;
        }
        *(float4*)&qout[(size_t)n * 16 + j4 * 4] = ov;
    }
}

// ---------------- W1 -> fp16 transposed [n][k] ----------------
__global__ void k_wconv(const float* __restrict__ W1) {
    int i = blockIdx.x * 256 + threadIdx.x;
    if (i < 64 * 512) {
        int n = i >> 9, k = i & 511;
        g_wth[i] = __float2half(W1[k * 64 + n]);
    }
}

// ---------------- GEMM (fp16 TC, depth-2 register pipeline, triple smem) ----------------
// Loads for tile kt+3 are issued at end of iter kt and committed to smem at end
// of iter kt+2 -> 2 staging sets (8 LDG.128/thread) in flight => ~2x MLP of R11.
#define GBM 128
__device__ __forceinline__ void gemm_ldx(const float* __restrict__ x, int row0,
                                         int kt, int tid, uint2* xs, uint4* wvr) {
    int k0 = kt * 32;
    #pragma unroll
    for (int i = 0; i < 4; i++) {
        int f = tid + i * 256;
        int r = f >> 3, c4 = (f & 7) << 2;
        float4 v = make_float4(0.f, 0.f, 0.f, 0.f);
        if (row0 + r < NP) v = *(const float4*)&x[(size_t)(row0 + r) * 512 + k0 + c4];
        __half2 h0 = __floats2half2_rn(v.x, v.y);
        __half2 h1 = __floats2half2_rn(v.z, v.w);
        xs[i] = make_uint2(*(unsigned*)&h0, *(unsigned*)&h1);
    }
    int n = tid >> 2, kc = (tid & 3) * 8;
    *wvr = *(const uint4*)&g_wth[n * 512 + k0 + kc];
}

__global__ __launch_bounds__(256, 2) void k_gemm1(const float* __restrict__ x,
                                                  const float* __restrict__ att_s,
                                                  const float* __restrict__ att_d) {
    __shared__ __half Xh[3][GBM][40];
    __shared__ __half Wts[3][64][40];
    int tid = threadIdx.x;
    int lane = tid & 31;
    int w = tid >> 5;
    int la3 = lane & 3, l4 = lane >> 2;
    int row0 = blockIdx.x * GBM;
    float acc[8][4] = {};
    uint2 xsA[4], xsB[4]; uint4 wA, wB;

    #define GEMM_STORE(st, xs, wv) do {                                        \
        _Pragma("unroll")                                                      \
        for (int i = 0; i < 4; i++) {                                          \
            int f = tid + i * 256;                                             \
            int r = f >> 3, c4 = (f & 7) << 2;                                 \
            *(uint2*)&Xh[st][r][c4] = (xs)[i];                                 \
        }                                                                      \
        { int n = tid >> 2, kc = (tid & 3) * 8;                                \
          *(uint2*)&Wts[st][n][kc]     = make_uint2((wv).x, (wv).y);           \
          *(uint2*)&Wts[st][n][kc + 4] = make_uint2((wv).z, (wv).w); }         \
    } while (0)

    #define GEMM_MMA(st) do {                                                  \
        _Pragma("unroll")                                                      \
        for (int ks = 0; ks < 2; ks++) {                                       \
            int kk = ks * 16 + la3 * 2;                                        \
            unsigned a[4], bfr[8][2];                                          \
            int r = w * 16 + l4;                                               \
            a[0] = *(unsigned*)&Xh[st][r][kk];                                 \
            a[1] = *(unsigned*)&Xh[st][r + 8][kk];                             \
            a[2] = *(unsigned*)&Xh[st][r][kk + 8];                             \
            a[3] = *(unsigned*)&Xh[st][r + 8][kk + 8];                         \
            _Pragma("unroll")                                                  \
            for (int n = 0; n < 8; n++) {                                      \
                int nn = n * 8 + l4;                                           \
                bfr[n][0] = *(unsigned*)&Wts[st][nn][kk];                      \
                bfr[n][1] = *(unsigned*)&Wts[st][nn][kk + 8];                  \
            }                                                                  \
            _Pragma("unroll")                                                  \
            for (int n = 0; n < 8; n++)                                        \
                asm volatile(                                                  \
                    "mma.sync.aligned.m16n8k16.row.col.f32.f16.f16.f32 "       \
                    "{%0,%1,%2,%3}, {%4,%5,%6,%7}, {%8,%9}, {%0,%1,%2,%3};\n"  \
                    : "+f"(acc[n][0]), "+f"(acc[n][1]),                        \
                      "+f"(acc[n][2]), "+f"(acc[n][3])                         \
                    : "r"(a[0]), "r"(a[1]), "r"(a[2]), "r"(a[3]),              \
                      "r"(bfr[n][0]), "r"(bfr[n][1]));                         \
        }                                                                      \
    } while (0)

    // prologue: t0 -> smem0; t1 -> regsA; t2 -> regsB (in flight through iter 0)
    gemm_ldx(x, row0, 0, tid, xsA, &wA);
    GEMM_STORE(0, xsA, wA);
    gemm_ldx(x, row0, 1, tid, xsA, &wA);
    gemm_ldx(x, row0, 2, tid, xsB, &wB);
    __syncthreads();

    #pragma unroll
    for (int kt = 0; kt < 16; kt += 2) {
        // even iter: MMA smem[kt%3]; commit regsA(tile kt+1); refill A with kt+3
        GEMM_MMA(kt % 3);
        if (kt + 1 < 16) {
            GEMM_STORE((kt + 1) % 3, xsA, wA);
            __syncthreads();
            if (kt + 3 < 16) gemm_ldx(x, row0, kt + 3, tid, xsA, &wA);
        }
        // odd iter: MMA smem[(kt+1)%3]; commit regsB(tile kt+2); refill B with kt+4
        if (kt + 1 < 16) {
            GEMM_MMA((kt + 1) % 3);
            if (kt + 2 < 16) {
                GEMM_STORE((kt + 2) % 3, xsB, wB);
                __syncthreads();
                if (kt + 4 < 16) gemm_ldx(x, row0, kt + 4, tid, xsB, &wB);
            }
        }
    }

    // epilogue: store h fp16 + fused per-head logits
    __half* hbase = (__half*)g_hv;
    float ats[16], atd[16];
    #pragma unroll
    for (int n = 0; n < 8; n++) {
        int col = n * 8 + la3 * 2;
        ats[n * 2]     = __ldg(&att_s[col]);
        ats[n * 2 + 1] = __ldg(&att_s[col + 1]);
        atd[n * 2]     = __ldg(&att_d[col]);
        atd[n * 2 + 1] = __ldg(&att_d[col + 1]);
    }
    #pragma unroll
    for (int rh = 0; rh < 2; rh++) {
        int row = row0 + w * 16 + rh * 8 + l4;
        bool ok = (row < NP);
        #pragma unroll
        for (int n = 0; n < 8; n++) {
            float c0 = acc[n][rh * 2 + 0];
            float c1 = acc[n][rh * 2 + 1];
            if (ok) {
                __half2 hp = __floats2half2_rn(c0, c1);
                *(__half2*)&hbase[(size_t)row * 64 + n * 8 + la3 * 2] = hp;
            }
            float ss = c0 * ats[n * 2] + c1 * ats[n * 2 + 1];
            float dd = c0 * atd[n * 2] + c1 * atd[n * 2 + 1];
            ss += __shfl_xor_sync(0xffffffffu, ss, 1);
            ss += __shfl_xor_sync(0xffffffffu, ss, 2);
            dd += __shfl_xor_sync(0xffffffffu, dd, 1);
            dd += __shfl_xor_sync(0xffffffffu, dd, 2);
            if (ok && la3 == 0) {
                g_as1[(size_t)row * 8 + n] = ss;
                g_ad1[(size_t)row * 8 + n] = dd;
            }
        }
    }
}

// ---------------- GAT layer 1: half-warp per edge, 4 channels/lane (R11) ----------------
__global__ __launch_bounds__(256) void k_gat1(const float* __restrict__ b1,
                                              const float* __restrict__ W2,
                                              const float* __restrict__ as2att,
                                              const float* __restrict__ ad2att) {
    __shared__ float vs[64], vd[64];
    if (threadIdx.x < 64) {
        int c = threadIdx.x;
        float s = 0.f, d = 0.f;
        #pragma unroll
        for (int j = 0; j < 16; j++) {
            float wv = __ldg(&W2[c * 16 + j]);
            s = fmaf(wv, __ldg(&as2att[j]), s);
            d = fmaf(wv, __ldg(&ad2att[j]), d);
        }
        vs[c] = s; vd[c] = d;
    }
    __syncthreads();
    int warp = (blockIdx.x * blockDim.x + threadIdx.x) >> 5;
    int lane = threadIdx.x & 31;
    if (warp >= NP) return;
    int dst = warp;
    int s = g_poff[dst], cnt = g_pcnt[dst];
    const int* bp = &g_psrc[s];
    int half = lane >> 4, hl = lane & 15;
    int c0 = hl * 4;
    int head = hl >> 1;
    const uint2* hb2 = (const uint2*)g_hv;
    float adv = g_ad1[dst * 8 + head];
    float den = 0.f, a0 = 0.f, a1 = 0.f, a2 = 0.f, a3 = 0.f;
    int j = 0;
    for (; j + 3 < cnt; j += 4) {
        int s0 = bp[j + half], s1 = bp[j + 2 + half];
        float x0 = g_as1[s0 * 8 + head];
        float x1 = g_as1[s1 * 8 + head];
        uint2 r0 = hb2[(size_t)s0 * 16 + hl];
        uint2 r1 = hb2[(size_t)s1 * 16 + hl];
        float w0 = __expf(leaky(x0 + adv));
        float w1 = __expf(leaky(x1 + adv));
        float2 f00 = __half22float2(*(__half2*)&r0.x);
        float2 f01 = __half22float2(*(__half2*)&r0.y);
        float2 f10 = __half22float2(*(__half2*)&r1.x);
        float2 f11 = __half22float2(*(__half2*)&r1.y);
        den += w0 + w1;
        a0 = fmaf(w0, f00.x, a0); a1 = fmaf(w0, f00.y, a1);
        a2 = fmaf(w0, f01.x, a2); a3 = fmaf(w0, f01.y, a3);
        a0 = fmaf(w1, f10.x, a0); a1 = fmaf(w1, f10.y, a1);
        a2 = fmaf(w1, f11.x, a2); a3 = fmaf(w1, f11.y, a3);
    }
    for (; j < cnt; j += 2) {
        int e = j + half;
        if (e < cnt) {
            int s0 = bp[e];
            float x0 = g_as1[s0 * 8 + head];
            uint2 r0 = hb2[(size_t)s0 * 16 + hl];
            float w0 = __expf(leaky(x0 + adv));
            float2 f00 = __half22float2(*(__half2*)&r0.x);
            float2 f01 = __half22float2(*(__half2*)&r0.y);
            den += w0;
            a0 = fmaf(w0, f00.x, a0); a1 = fmaf(w0, f00.y, a1);
            a2 = fmaf(w0, f01.x, a2); a3 = fmaf(w0, f01.y, a3);
        }
    }
    a0 += __shfl_xor_sync(0xffffffffu, a0, 16);
    a1 += __shfl_xor_sync(0xffffffffu, a1, 16);
    a2 += __shfl_xor_sync(0xffffffffu, a2, 16);
    a3 += __shfl_xor_sync(0xffffffffu, a3, 16);
    den += __shfl_xor_sync(0xffffffffu, den, 16);
    float inv = 1.0f / (den + 1e-16f);
    float4 bv = *(const float4*)&b1[c0];
    a0 = a0 * inv + bv.x; a1 = a1 * inv + bv.y;
    a2 = a2 * inv + bv.z; a3 = a3 * inv + bv.w;
    a0 = a0 > 0.f ? a0 : (__expf(a0) - 1.f);   // ELU
    a1 = a1 > 0.f ? a1 : (__expf(a1) - 1.f);
    a2 = a2 > 0.f ? a2 : (__expf(a2) - 1.f);
    a3 = a3 > 0.f ? a3 : (__expf(a3) - 1.f);
    if (lane < 16) {
        __half2 h01 = __floats2half2_rn(a0, a1);
        __half2 h23 = __floats2half2_rn(a2, a3);
        ((uint2*)g_heluv)[(size_t)dst * 16 + hl] =
            make_uint2(*(unsigned*)&h01, *(unsigned*)&h23);
    }
    float ss = a0 * vs[c0] + a1 * vs[c0 + 1] + a2 * vs[c0 + 2] + a3 * vs[c0 + 3];
    float dd = a0 * vd[c0] + a1 * vd[c0 + 1] + a2 * vd[c0 + 2] + a3 * vd[c0 + 3];
    #pragma unroll
    for (int o = 8; o > 0; o >>= 1) {
        ss += __shfl_xor_sync(0xffffffffu, ss, o);
        dd += __shfl_xor_sync(0xffffffffu, dd, o);
    }
    if (lane == 0) { g_as2[dst] = ss; g_ad2[dst] = dd; }
}

// ---------------- GAT layer 2: half-warp per edge, 4 channels/lane (R11) ----------------
__global__ __launch_bounds__(256) void k_gat2(const float* __restrict__ W2,
                                              const float* __restrict__ b2,
                                              float* __restrict__ out) {
    __shared__ float W2s[64 * 16];
    __shared__ float accs[8][64];
    for (int i = threadIdx.x; i < 64 * 16; i += blockDim.x) W2s[i] = W2[i];
    __syncthreads();
    int warp = (blockIdx.x * blockDim.x + threadIdx.x) >> 5;
    int lane = threadIdx.x & 31;
    int wip = (threadIdx.x >> 5);
    if (warp >= NP) return;
    int dst = warp;
    int s = g_poff[dst], cnt = g_pcnt[dst];
    const int* bp = &g_psrc[s];
    int half = lane >> 4, hl = lane & 15;
    int c0 = hl * 4;
    const uint2* hb2 = (const uint2*)g_heluv;
    float adv = g_ad2[dst];
    float den = 0.f, a0 = 0.f, a1 = 0.f, a2 = 0.f, a3 = 0.f;
    int j = 0;
    for (; j + 3 < cnt; j += 4) {
        int s0 = bp[j + half], s1 = bp[j + 2 + half];
        float x0 = g_as2[s0], x1 = g_as2[s1];
        uint2 r0 = hb2[(size_t)s0 * 16 + hl];
        uint2 r1 = hb2[(size_t)s1 * 16 + hl];
        float w0 = __expf(leaky(x0 + adv));
        float w1 = __expf(leaky(x1 + adv));
        float2 f00 = __half22float2(*(__half2*)&r0.x);
        float2 f01 = __half22float2(*(__half2*)&r0.y);
        float2 f10 = __half22float2(*(__half2*)&r1.x);
        float2 f11 = __half22float2(*(__half2*)&r1.y);
        den += w0 + w1;
        a0 = fmaf(w0, f00.x, a0); a1 = fmaf(w0, f00.y, a1);
        a2 = fmaf(w0, f01.x, a2); a3 = fmaf(w0, f01.y, a3);
        a0 = fmaf(w1, f10.x, a0); a1 = fmaf(w1, f10.y, a1);
        a2 = fmaf(w1, f11.x, a2); a3 = fmaf(w1, f11.y, a3);
    }
    for (; j < cnt; j += 2) {
        int e = j + half;
        if (e < cnt) {
            int s0 = bp[e];
            float x0 = g_as2[s0];
            uint2 r0 = hb2[(size_t)s0 * 16 + hl];
            float w0 = __expf(leaky(x0 + adv));
            float2 f00 = __half22float2(*(__half2*)&r0.x);
            float2 f01 = __half22float2(*(__half2*)&r0.y);
            den += w0;
            a0 = fmaf(w0, f00.x, a0); a1 = fmaf(w0, f00.y, a1);
            a2 = fmaf(w0, f01.x, a2); a3 = fmaf(w0, f01.y, a3);
        }
    }
    a0 += __shfl_xor_sync(0xffffffffu, a0, 16);
    a1 += __shfl_xor_sync(0xffffffffu, a1, 16);
    a2 += __shfl_xor_sync(0xffffffffu, a2, 16);
    a3 += __shfl_xor_sync(0xffffffffu, a3, 16);
    den += __shfl_xor_sync(0xffffffffu, den, 16);
    float inv = 1.0f / (den + 1e-16f);
    if (lane < 16) {
        accs[wip][c0]     = a0 * inv;
        accs[wip][c0 + 1] = a1 * inv;
        accs[wip][c0 + 2] = a2 * inv;
        accs[wip][c0 + 3] = a3 * inv;
    }
    __syncwarp();
    if (lane < 16) {
        float o = __ldg(&b2[lane]);
        #pragma unroll
        for (int c = 0; c < 64; c++) o = fmaf(accs[wip][c], W2s[c * 16 + lane], o);
        out[dst * 16 + lane] = o;
    }
}

// ---------------- launcher: forked-stream graph (R11) ----------------
extern "C" void kernel_launch(void* const* d_in, const int* in_sizes, int n_in,
                              void* d_out, int out_size) {
    const float* x    = (const float*)d_in[0];
    const int*   ei   = (const int*)d_in[1];
    const float* dx   = (const float*)d_in[2];
    const int*   dei  = (const int*)d_in[3];
    const float* W1   = (const float*)d_in[4];
    const float* as1a = (const float*)d_in[5];
    const float* ad1a = (const float*)d_in[6];
    const float* b1   = (const float*)d_in[7];
    const float* W2   = (const float*)d_in[8];
    const float* as2a = (const float*)d_in[9];
    const float* ad2a = (const float*)d_in[10];
    const float* b2   = (const float*)d_in[11];
    const float* Wg1  = (const float*)d_in[12];
    const float* bg1  = (const float*)d_in[13];
    const float* Wg2  = (const float*)d_in[14];
    const float* bg2  = (const float*)d_in[15];
    float* out = (float*)d_out;              // [NP,16] then [NDU,16]
    float* qout = out + (size_t)NP * 16;

    static cudaStream_t s1 = nullptr;
    static cudaEvent_t ev_fork = nullptr, ev_fill = nullptr, ev_done = nullptr;
    static void *p_pcnt = nullptr, *p_dcnt = nullptr, *p_cur = nullptr;
    if (!s1) {
        cudaStreamCreateWithFlags(&s1, cudaStreamNonBlocking);
        cudaEventCreateWithFlags(&ev_fork, cudaEventDisableTiming);
        cudaEventCreateWithFlags(&ev_fill, cudaEventDisableTiming);
        cudaEventCreateWithFlags(&ev_done, cudaEventDisableTiming);
        cudaGetSymbolAddress(&p_pcnt, g_pcnt);
        cudaGetSymbolAddress(&p_dcnt, g_dcnt);
        cudaGetSymbolAddress(&p_cur, g_cursor);
    }

    // zero counters via memset nodes
    cudaMemsetAsync(p_pcnt, 0, NP * sizeof(int), 0);
    cudaMemsetAsync(p_dcnt, 0, NDU * sizeof(int), 0);
    cudaMemsetAsync(p_cur, 0, 2 * sizeof(int), 0);

    cudaEventRecord(ev_fork, 0);
    cudaStreamWaitEvent(s1, ev_fork, 0);

    // stream 0: CSR build; s1: W-convert + GEMM
    k_hist<<<(EDT + 255) / 256, 256>>>(ei, dei);                            // k0
    k_wconv<<<128, 256, 0, s1>>>(W1);                                       // k1
    k_alloc<<<NPB + NDB, 1024>>>(dx);                                       // k2
    k_gemm1<<<(NP + GBM - 1) / GBM, 256, 0, s1>>>(x, as1a, ad1a);           // k3 <- profiled
    k_fill<<<(EDT + 255) / 256, 256>>>(ei, dei);                            // k4
    cudaEventRecord(ev_fill, 0);

    // s1: GAT branch
    cudaStreamWaitEvent(s1, ev_fill, 0);
    k_gat1<<<(NP * 32 + 255) / 256, 256, 0, s1>>>(b1, W2, as2a, ad2a);      // k5
    k_gat2<<<(NP * 32 + 255) / 256, 256, 0, s1>>>(W2, b2, out);             // k6

    // stream 0: dual GCN (overlaps GAT)
    k_gcn1<<<(NDU + 255) / 256, 256>>>(Wg1, bg1);                           // k7
    k_gcn2<<<(NDU + 255) / 256, 256>>>(Wg2, bg2, qout);                     // k8

    cudaEventRecord(ev_done, s1);
    cudaStreamWaitEvent(0, ev_done, 0);
}

// round 15
// speedup vs baseline: 1.3436x; 1.0102x over previous
#include <cuda_runtime.h>
#include <cuda_fp16.h>
#include <math.h>

// Problem constants
#define NP   100000      // primal nodes
#define EPn  1600000     // primal edges
#define NDU  1600000     // dual nodes
#define EDU  3200000     // dual edges
#define EPT  (EPn + NP)  // primal edges + self loops
#define EDT  (EDU + NDU) // dual edges + self loops
#define NEG_SLOPE 0.2f

// -------- static device scratch --------
__device__ int   g_pcnt[NP], g_poff[NP], g_pfill[NP];
__device__ int   g_dcnt[NDU], g_doff[NDU], g_dfill[NDU];
__device__ int   g_psrc[EPT];
__device__ int   g_dsrc[EDT];
__device__ int   g_cursor[2];
__device__ float g_dinv[NDU];
__device__ uint2 g_xsv[NDU];        // half4: dinv[n]*dx[n][0..3]
__device__ uint4 g_hv[NP * 8];      // x @ W1, half[NP][64]
__device__ uint4 g_heluv[NP * 8];   // elu(GAT1 out), half[NP][64]
__device__ uint4 g_q1v[NDU];        // dinv[n]*relu(GCN1 out), half[NDU][8]
__device__ float g_as1[NP * 8], g_ad1[NP * 8];
__device__ float g_as2[NP], g_ad2[NP];
__device__ __half g_wth[64 * 512];  // W1 transposed fp16: [n][k]

__device__ __forceinline__ float leaky(float e) { return e > 0.f ? e : NEG_SLOPE * e; }

// ---------------- CSR (dense combined — R14) ----------------
__global__ void k_hist(const int* __restrict__ ei, const int* __restrict__ dei) {
    int i = blockIdx.x * blockDim.x + threadIdx.x;
    if (i < EPT) {
        int dst = (i < EPn) ? ei[EPn + i] : (i - EPn);
        atomicAdd(&g_pcnt[dst], 1);
    }
    if (i < EDT) {
        int dst = (i < EDU) ? dei[EDU + i] : (i - EDU);
        atomicAdd(&g_dcnt[dst], 1);
    }
}

__device__ __forceinline__ void alloc_body(const int* __restrict__ cnt,
                                           int* __restrict__ off,
                                           int* __restrict__ fill,
                                           int n, int curIdx, int doDinv, int bid,
                                           const float* __restrict__ dx) {
    __shared__ int sh[1024];
    __shared__ int base;
    int t = threadIdx.x;
    int i = bid * 1024 + t;
    int v = (i < n) ? cnt[i] : 0;
    sh[t] = v;
    __syncthreads();
    #pragma unroll
    for (int d = 1; d < 1024; d <<= 1) {
        int add = (t >= d) ? sh[t - d] : 0;
        __syncthreads();
        sh[t] += add;
        __syncthreads();
    }
    if (t == 1023) base = atomicAdd(&g_cursor[curIdx], sh[1023]);
    __syncthreads();
    if (i < n) {
        int o = base + sh[t] - v;   // exclusive
        off[i] = o;
        fill[i] = o;
        if (doDinv) {
            float di = rsqrtf((float)(v > 0 ? v : 1));
            g_dinv[i] = di;
            float4 xv = *(const float4*)&dx[(size_t)i * 4];
            __half2 a = __floats2half2_rn(di * xv.x, di * xv.y);
            __half2 b = __floats2half2_rn(di * xv.z, di * xv.w);
            g_xsv[i] = make_uint2(*(unsigned*)&a, *(unsigned*)&b);
        }
    }
}
#define NPB 98     // ceil(NP/1024)
#define NDB 1563   // ceil(NDU/1024)
__global__ void k_alloc(const float* __restrict__ dx) {
    if (blockIdx.x < NPB) alloc_body(g_pcnt, g_poff, g_pfill, NP, 0, 0, blockIdx.x, dx);
    else                  alloc_body(g_dcnt, g_doff, g_dfill, NDU, 1, 1, blockIdx.x - NPB, dx);
}

__global__ void k_fill(const int* __restrict__ ei, const int* __restrict__ dei) {
    int i = blockIdx.x * blockDim.x + threadIdx.x;
    if (i < EPT) {
        int src, dst;
        if (i < EPn) { src = ei[i]; dst = ei[EPn + i]; }
        else         { src = dst = i - EPn; }
        int pos = atomicAdd(&g_pfill[dst], 1);
        g_psrc[pos] = src;
    }
    if (i < EDT) {
        int src, dst;
        if (i < EDU) { src = dei[i]; dst = dei[EDU + i]; }
        else         { src = dst = i - EDU; }
        int pos = atomicAdd(&g_dfill[dst], 1);
        g_dsrc[pos] = src;
    }
}

// ---------------- dual GCN layer 1 (src prefetch restored) ----------------
__global__ void k_gcn1(const float* __restrict__ Wg1, const float* __restrict__ bg1) {
    int n = blockIdx.x * blockDim.x + threadIdx.x;
    if (n >= NDU) return;
    int s = g_doff[n], cnt = g_dcnt[n];
    float4 acc = make_float4(0.f, 0.f, 0.f, 0.f);
    int e = s + cnt;
    int src = (s < e) ? g_dsrc[s] : 0;
    for (int j = s; j < e; j++) {
        int nsrc = (j + 1 < e) ? g_dsrc[j + 1] : 0;
        uint2 r = g_xsv[src];
        float2 f0 = __half22float2(*(__half2*)&r.x);
        float2 f1 = __half22float2(*(__half2*)&r.y);
        acc.x += f0.x; acc.y += f0.y; acc.z += f1.x; acc.w += f1.y;
        src = nsrc;
    }
    float di = g_dinv[n];
    acc.x *= di; acc.y *= di; acc.z *= di; acc.w *= di;
    float o[8];
    #pragma unroll
    for (int j = 0; j < 8; j++) {
        float v = __ldg(&bg1[j]);
        v = fmaf(acc.x, __ldg(&Wg1[0 * 8 + j]), v);
        v = fmaf(acc.y, __ldg(&Wg1[1 * 8 + j]), v);
        v = fmaf(acc.z, __ldg(&Wg1[2 * 8 + j]), v);
        v = fmaf(acc.w, __ldg(&Wg1[3 * 8 + j]), v);
        v = v > 0.f ? v : 0.f;     // ReLU
        o[j] = v * di;             // fold dinv[n] for layer 2
    }
    __half2 p0 = __floats2half2_rn(o[0], o[1]);
    __half2 p1 = __floats2half2_rn(o[2], o[3]);
    __half2 p2 = __floats2half2_rn(o[4], o[5]);
    __half2 p3 = __floats2half2_rn(o[6], o[7]);
    uint4 pk;
    pk.x = *(unsigned*)&p0; pk.y = *(unsigned*)&p1;
    pk.z = *(unsigned*)&p2; pk.w = *(unsigned*)&p3;
    g_q1v[n] = pk;
}

// ---------------- dual GCN layer 2 (src prefetch restored) ----------------
__global__ void k_gcn2(const float* __restrict__ Wg2, const float* __restrict__ bg2,
                       float* __restrict__ qout) {
    int n = blockIdx.x * blockDim.x + threadIdx.x;
    if (n >= NDU) return;
    int s = g_doff[n], cnt = g_dcnt[n];
    float acc[8] = {};
    int e = s + cnt;
    int src = (s < e) ? g_dsrc[s] : 0;
    for (int j = s; j < e; j++) {
        int nsrc = (j + 1 < e) ? g_dsrc[j + 1] : 0;
        uint4 raw = g_q1v[src];
        float2 f0 = __half22float2(*(__half2*)&raw.x);
        float2 f1 = __half22float2(*(__half2*)&raw.y);
        float2 f2 = __half22float2(*(__half2*)&raw.z);
        float2 f3 = __half22float2(*(__half2*)&raw.w);
        acc[0] += f0.x; acc[1] += f0.y;
        acc[2] += f1.x; acc[3] += f1.y;
        acc[4] += f2.x; acc[5] += f2.y;
        acc[6] += f3.x; acc[7] += f3.y;
        src = nsrc;
    }
    float di = g_dinv[n];
    #pragma unroll
    for (int i = 0; i < 8; i++) acc[i] *= di;
    #pragma unroll
    for (int j4 = 0; j4 < 4; j4++) {
        float4 ov;
        float* op = (float*)&ov;
        #pragma unroll
        for (int t = 0; t < 4; t++) {
            int j = j4 * 4 + t;
            float v = __ldg(&bg2[j]);
            #pragma unroll
            for (int i = 0; i < 8; i++) v = fmaf(acc[i], __ldg(&Wg2[i * 16 + j]), v);
            op[t] = v;
        }
        *(float4*)&qout[(size_t)n * 16 + j4 * 4] = ov;
    }
}

// ---------------- W1 -> fp16 transposed [n][k] ----------------
__global__ void k_wconv(const float* __restrict__ W1) {
    int i = blockIdx.x * 256 + threadIdx.x;
    if (i < 64 * 512) {
        int n = i >> 9, k = i & 511;
        g_wth[i] = __float2half(W1[k * 64 + n]);
    }
}

// ---------------- GEMM (fp16 TC, depth-2 register pipeline, triple smem — R14) ----------------
#define GBM 128
__device__ __forceinline__ void gemm_ldx(const float* __restrict__ x, int row0,
                                         int kt, int tid, uint2* xs, uint4* wvr) {
    int k0 = kt * 32;
    #pragma unroll
    for (int i = 0; i < 4; i++) {
        int f = tid + i * 256;
        int r = f >> 3, c4 = (f & 7) << 2;
        float4 v = make_float4(0.f, 0.f, 0.f, 0.f);
        if (row0 + r < NP) v = *(const float4*)&x[(size_t)(row0 + r) * 512 + k0 + c4];
        __half2 h0 = __floats2half2_rn(v.x, v.y);
        __half2 h1 = __floats2half2_rn(v.z, v.w);
        xs[i] = make_uint2(*(unsigned*)&h0, *(unsigned*)&h1);
    }
    int n = tid >> 2, kc = (tid & 3) * 8;
    *wvr = *(const uint4*)&g_wth[n * 512 + k0 + kc];
}

__global__ __launch_bounds__(256, 2) void k_gemm1(const float* __restrict__ x,
                                                  const float* __restrict__ att_s,
                                                  const float* __restrict__ att_d) {
    __shared__ __half Xh[3][GBM][40];
    __shared__ __half Wts[3][64][40];
    int tid = threadIdx.x;
    int lane = tid & 31;
    int w = tid >> 5;
    int la3 = lane & 3, l4 = lane >> 2;
    int row0 = blockIdx.x * GBM;
    float acc[8][4] = {};
    uint2 xsA[4], xsB[4]; uint4 wA, wB;

    #define GEMM_STORE(st, xs, wv) do {                                        \
        _Pragma("unroll")                                                      \
        for (int i = 0; i < 4; i++) {                                          \
            int f = tid + i * 256;                                             \
            int r = f >> 3, c4 = (f & 7) << 2;                                 \
            *(uint2*)&Xh[st][r][c4] = (xs)[i];                                 \
        }                                                                      \
        { int n = tid >> 2, kc = (tid & 3) * 8;                                \
          *(uint2*)&Wts[st][n][kc]     = make_uint2((wv).x, (wv).y);           \
          *(uint2*)&Wts[st][n][kc + 4] = make_uint2((wv).z, (wv).w); }         \
    } while (0)

    #define GEMM_MMA(st) do {                                                  \
        _Pragma("unroll")                                                      \
        for (int ks = 0; ks < 2; ks++) {                                       \
            int kk = ks * 16 + la3 * 2;                                        \
            unsigned a[4], bfr[8][2];                                          \
            int r = w * 16 + l4;                                               \
            a[0] = *(unsigned*)&Xh[st][r][kk];                                 \
            a[1] = *(unsigned*)&Xh[st][r + 8][kk];                             \
            a[2] = *(unsigned*)&Xh[st][r][kk + 8];                             \
            a[3] = *(unsigned*)&Xh[st][r + 8][kk + 8];                         \
            _Pragma("unroll")                                                  \
            for (int n = 0; n < 8; n++) {                                      \
                int nn = n * 8 + l4;                                           \
                bfr[n][0] = *(unsigned*)&Wts[st][nn][kk];                      \
                bfr[n][1] = *(unsigned*)&Wts[st][nn][kk + 8];                  \
            }                                                                  \
            _Pragma("unroll")                                                  \
            for (int n = 0; n < 8; n++)                                        \
                asm volatile(                                                  \
                    "mma.sync.aligned.m16n8k16.row.col.f32.f16.f16.f32 "       \
                    "{%0,%1,%2,%3}, {%4,%5,%6,%7}, {%8,%9}, {%0,%1,%2,%3};\n"  \
                    : "+f"(acc[n][0]), "+f"(acc[n][1]),                        \
                      "+f"(acc[n][2]), "+f"(acc[n][3])                         \
                    : "r"(a[0]), "r"(a[1]), "r"(a[2]), "r"(a[3]),              \
                      "r"(bfr[n][0]), "r"(bfr[n][1]));                         \
        }                                                                      \
    } while (0)

    // prologue: t0 -> smem0; t1 -> regsA; t2 -> regsB
    gemm_ldx(x, row0, 0, tid, xsA, &wA);
    GEMM_STORE(0, xsA, wA);
    gemm_ldx(x, row0, 1, tid, xsA, &wA);
    gemm_ldx(x, row0, 2, tid, xsB, &wB);
    __syncthreads();

    #pragma unroll
    for (int kt = 0; kt < 16; kt += 2) {
        GEMM_MMA(kt % 3);
        if (kt + 1 < 16) {
            GEMM_STORE((kt + 1) % 3, xsA, wA);
            __syncthreads();
            if (kt + 3 < 16) gemm_ldx(x, row0, kt + 3, tid, xsA, &wA);
        }
        if (kt + 1 < 16) {
            GEMM_MMA((kt + 1) % 3);
            if (kt + 2 < 16) {
                GEMM_STORE((kt + 2) % 3, xsB, wB);
                __syncthreads();
                if (kt + 4 < 16) gemm_ldx(x, row0, kt + 4, tid, xsB, &wB);
            }
        }
    }

    // epilogue: store h fp16 + fused per-head logits
    __half* hbase = (__half*)g_hv;
    float ats[16], atd[16];
    #pragma unroll
    for (int n = 0; n < 8; n++) {
        int col = n * 8 + la3 * 2;
        ats[n * 2]     = __ldg(&att_s[col]);
        ats[n * 2 + 1] = __ldg(&att_s[col + 1]);
        atd[n * 2]     = __ldg(&att_d[col]);
        atd[n * 2 + 1] = __ldg(&att_d[col + 1]);
    }
    #pragma unroll
    for (int rh = 0; rh < 2; rh++) {
        int row = row0 + w * 16 + rh * 8 + l4;
        bool ok = (row < NP);
        #pragma unroll
        for (int n = 0; n < 8; n++) {
            float c0 = acc[n][rh * 2 + 0];
            float c1 = acc[n][rh * 2 + 1];
            if (ok) {
                __half2 hp = __floats2half2_rn(c0, c1);
                *(__half2*)&hbase[(size_t)row * 64 + n * 8 + la3 * 2] = hp;
            }
            float ss = c0 * ats[n * 2] + c1 * ats[n * 2 + 1];
            float dd = c0 * atd[n * 2] + c1 * atd[n * 2 + 1];
            ss += __shfl_xor_sync(0xffffffffu, ss, 1);
            ss += __shfl_xor_sync(0xffffffffu, ss, 2);
            dd += __shfl_xor_sync(0xffffffffu, dd, 1);
            dd += __shfl_xor_sync(0xffffffffu, dd, 2);
            if (ok && la3 == 0) {
                g_as1[(size_t)row * 8 + n] = ss;
                g_ad1[(size_t)row * 8 + n] = dd;
            }
        }
    }
}

// ---------------- GAT layer 1: half-warp/edge, 2-stage gather pipeline ----------------
// Per iteration: issue INDEX loads for trip t+2, DATA loads for trip t+1
// (indices landed last iter), compute trip t. Both latency levels hidden.
__global__ __launch_bounds__(256) void k_gat1(const float* __restrict__ b1,
                                              const float* __restrict__ W2,
                                              const float* __restrict__ as2att,
                                              const float* __restrict__ ad2att) {
    __shared__ float vs[64], vd[64];
    if (threadIdx.x < 64) {
        int c = threadIdx.x;
        float s = 0.f, d = 0.f;
        #pragma unroll
        for (int j = 0; j < 16; j++) {
            float wv = __ldg(&W2[c * 16 + j]);
            s = fmaf(wv, __ldg(&as2att[j]), s);
            d = fmaf(wv, __ldg(&ad2att[j]), d);
        }
        vs[c] = s; vd[c] = d;
    }
    __syncthreads();
    int warp = (blockIdx.x * blockDim.x + threadIdx.x) >> 5;
    int lane = threadIdx.x & 31;
    if (warp >= NP) return;
    int dst = warp;
    int s = g_poff[dst], cnt = g_pcnt[dst];
    const int* bp = &g_psrc[s];
    int half = lane >> 4, hl = lane & 15;
    int c0 = hl * 4;
    int head = hl >> 1;
    const uint2* hb2 = (const uint2*)g_hv;
    float adv = g_ad1[dst * 8 + head];
    float den = 0.f, a0 = 0.f, a1 = 0.f, a2 = 0.f, a3 = 0.f;

    // pipeline state: data for current trip, indices for next trip
    float px0 = 0.f, px1 = 0.f;
    uint2 pr0 = make_uint2(0u, 0u), pr1 = make_uint2(0u, 0u);
    int n0 = 0, n1 = 0;
    if (cnt >= 4) {
        int i0 = bp[half], i1 = bp[2 + half];
        px0 = g_as1[i0 * 8 + head]; px1 = g_as1[i1 * 8 + head];
        pr0 = hb2[(size_t)i0 * 16 + hl]; pr1 = hb2[(size_t)i1 * 16 + hl];
        if (cnt >= 8) { n0 = bp[4 + half]; n1 = bp[6 + half]; }
    }
    int j = 0;
    for (; j + 3 < cnt; j += 4) {
        // stage 2: index loads for trip j+8
        int m0 = 0, m1 = 0;
        if (j + 11 < cnt) { m0 = bp[j + 8 + half]; m1 = bp[j + 10 + half]; }
        // stage 1: data loads for trip j+4 (indices n0/n1, landed last iter)
        float qx0 = 0.f, qx1 = 0.f;
        uint2 qr0 = make_uint2(0u, 0u), qr1 = make_uint2(0u, 0u);
        if (j + 7 < cnt) {
            qx0 = g_as1[n0 * 8 + head]; qx1 = g_as1[n1 * 8 + head];
            qr0 = hb2[(size_t)n0 * 16 + hl]; qr1 = hb2[(size_t)n1 * 16 + hl];
        }
        // stage 0: compute current trip
        float w0 = __expf(leaky(px0 + adv));
        float w1 = __expf(leaky(px1 + adv));
        float2 f00 = __half22float2(*(__half2*)&pr0.x);
        float2 f01 = __half22float2(*(__half2*)&pr0.y);
        float2 f10 = __half22float2(*(__half2*)&pr1.x);
        float2 f11 = __half22float2(*(__half2*)&pr1.y);
        den += w0 + w1;
        a0 = fmaf(w0, f00.x, a0); a1 = fmaf(w0, f00.y, a1);
        a2 = fmaf(w0, f01.x, a2); a3 = fmaf(w0, f01.y, a3);
        a0 = fmaf(w1, f10.x, a0); a1 = fmaf(w1, f10.y, a1);
        a2 = fmaf(w1, f11.x, a2); a3 = fmaf(w1, f11.y, a3);
        // rotate
        px0 = qx0; px1 = qx1; pr0 = qr0; pr1 = qr1;
        n0 = m0; n1 = m1;
    }
    for (; j < cnt; j += 2) {       // tail (up to 3 edges), guarded direct loads
        int e = j + half;
        if (e < cnt) {
            int s0 = bp[e];
            float x0 = g_as1[s0 * 8 + head];
            uint2 r0 = hb2[(size_t)s0 * 16 + hl];
            float w0 = __expf(leaky(x0 + adv));
            float2 f00 = __half22float2(*(__half2*)&r0.x);
            float2 f01 = __half22float2(*(__half2*)&r0.y);
            den += w0;
            a0 = fmaf(w0, f00.x, a0); a1 = fmaf(w0, f00.y, a1);
            a2 = fmaf(w0, f01.x, a2); a3 = fmaf(w0, f01.y, a3);
        }
    }
    a0 += __shfl_xor_sync(0xffffffffu, a0, 16);
    a1 += __shfl_xor_sync(0xffffffffu, a1, 16);
    a2 += __shfl_xor_sync(0xffffffffu, a2, 16);
    a3 += __shfl_xor_sync(0xffffffffu, a3, 16);
    den += __shfl_xor_sync(0xffffffffu, den, 16);
    float inv = 1.0f / (den + 1e-16f);
    float4 bv = *(const float4*)&b1[c0];
    a0 = a0 * inv + bv.x; a1 = a1 * inv + bv.y;
    a2 = a2 * inv + bv.z; a3 = a3 * inv + bv.w;
    a0 = a0 > 0.f ? a0 : (__expf(a0) - 1.f);   // ELU
    a1 = a1 > 0.f ? a1 : (__expf(a1) - 1.f);
    a2 = a2 > 0.f ? a2 : (__expf(a2) - 1.f);
    a3 = a3 > 0.f ? a3 : (__expf(a3) - 1.f);
    if (lane < 16) {
        __half2 h01 = __floats2half2_rn(a0, a1);
        __half2 h23 = __floats2half2_rn(a2, a3);
        ((uint2*)g_heluv)[(size_t)dst * 16 + hl] =
            make_uint2(*(unsigned*)&h01, *(unsigned*)&h23);
    }
    float ss = a0 * vs[c0] + a1 * vs[c0 + 1] + a2 * vs[c0 + 2] + a3 * vs[c0 + 3];
    float dd = a0 * vd[c0] + a1 * vd[c0 + 1] + a2 * vd[c0 + 2] + a3 * vd[c0 + 3];
    #pragma unroll
    for (int o = 8; o > 0; o >>= 1) {
        ss += __shfl_xor_sync(0xffffffffu, ss, o);
        dd += __shfl_xor_sync(0xffffffffu, dd, o);
    }
    if (lane == 0) { g_as2[dst] = ss; g_ad2[dst] = dd; }
}

// ---------------- GAT layer 2: half-warp/edge, 2-stage gather pipeline ----------------
__global__ __launch_bounds__(256) void k_gat2(const float* __restrict__ W2,
                                              const float* __restrict__ b2,
                                              float* __restrict__ out) {
    __shared__ float W2s[64 * 16];
    __shared__ float accs[8][64];
    for (int i = threadIdx.x; i < 64 * 16; i += blockDim.x) W2s[i] = W2[i];
    __syncthreads();
    int warp = (blockIdx.x * blockDim.x + threadIdx.x) >> 5;
    int lane = threadIdx.x & 31;
    int wip = (threadIdx.x >> 5);
    if (warp >= NP) return;
    int dst = warp;
    int s = g_poff[dst], cnt = g_pcnt[dst];
    const int* bp = &g_psrc[s];
    int half = lane >> 4, hl = lane & 15;
    int c0 = hl * 4;
    const uint2* hb2 = (const uint2*)g_heluv;
    float adv = g_ad2[dst];
    float den = 0.f, a0 = 0.f, a1 = 0.f, a2 = 0.f, a3 = 0.f;

    float px0 = 0.f, px1 = 0.f;
    uint2 pr0 = make_uint2(0u, 0u), pr1 = make_uint2(0u, 0u);
    int n0 = 0, n1 = 0;
    if (cnt >= 4) {
        int i0 = bp[half], i1 = bp[2 + half];
        px0 = g_as2[i0]; px1 = g_as2[i1];
        pr0 = hb2[(size_t)i0 * 16 + hl]; pr1 = hb2[(size_t)i1 * 16 + hl];
        if (cnt >= 8) { n0 = bp[4 + half]; n1 = bp[6 + half]; }
    }
    int j = 0;
    for (; j + 3 < cnt; j += 4) {
        int m0 = 0, m1 = 0;
        if (j + 11 < cnt) { m0 = bp[j + 8 + half]; m1 = bp[j + 10 + half]; }
        float qx0 = 0.f, qx1 = 0.f;
        uint2 qr0 = make_uint2(0u, 0u), qr1 = make_uint2(0u, 0u);
        if (j + 7 < cnt) {
            qx0 = g_as2[n0]; qx1 = g_as2[n1];
            qr0 = hb2[(size_t)n0 * 16 + hl]; qr1 = hb2[(size_t)n1 * 16 + hl];
        }
        float w0 = __expf(leaky(px0 + adv));
        float w1 = __expf(leaky(px1 + adv));
        float2 f00 = __half22float2(*(__half2*)&pr0.x);
        float2 f01 = __half22float2(*(__half2*)&pr0.y);
        float2 f10 = __half22float2(*(__half2*)&pr1.x);
        float2 f11 = __half22float2(*(__half2*)&pr1.y);
        den += w0 + w1;
        a0 = fmaf(w0, f00.x, a0); a1 = fmaf(w0, f00.y, a1);
        a2 = fmaf(w0, f01.x, a2); a3 = fmaf(w0, f01.y, a3);
        a0 = fmaf(w1, f10.x, a0); a1 = fmaf(w1, f10.y, a1);
        a2 = fmaf(w1, f11.x, a2); a3 = fmaf(w1, f11.y, a3);
        px0 = qx0; px1 = qx1; pr0 = qr0; pr1 = qr1;
        n0 = m0; n1 = m1;
    }
    for (; j < cnt; j += 2) {
        int e = j + half;
        if (e < cnt) {
            int s0 = bp[e];
            float x0 = g_as2[s0];
            uint2 r0 = hb2[(size_t)s0 * 16 + hl];
            float w0 = __expf(leaky(x0 + adv));
            float2 f00 = __half22float2(*(__half2*)&r0.x);
            float2 f01 = __half22float2(*(__half2*)&r0.y);
            den += w0;
            a0 = fmaf(w0, f00.x, a0); a1 = fmaf(w0, f00.y, a1);
            a2 = fmaf(w0, f01.x, a2); a3 = fmaf(w0, f01.y, a3);
        }
    }
    a0 += __shfl_xor_sync(0xffffffffu, a0, 16);
    a1 += __shfl_xor_sync(0xffffffffu, a1, 16);
    a2 += __shfl_xor_sync(0xffffffffu, a2, 16);
    a3 += __shfl_xor_sync(0xffffffffu, a3, 16);
    den += __shfl_xor_sync(0xffffffffu, den, 16);
    float inv = 1.0f / (den + 1e-16f);
    if (lane < 16) {
        accs[wip][c0]     = a0 * inv;
        accs[wip][c0 + 1] = a1 * inv;
        accs[wip][c0 + 2] = a2 * inv;
        accs[wip][c0 + 3] = a3 * inv;
    }
    __syncwarp();
    if (lane < 16) {
        float o = __ldg(&b2[lane]);
        #pragma unroll
        for (int c = 0; c < 64; c++) o = fmaf(accs[wip][c], W2s[c * 16 + lane], o);
        out[dst * 16 + lane] = o;
    }
}

// ---------------- launcher: forked-stream graph (R14) ----------------
extern "C" void kernel_launch(void* const* d_in, const int* in_sizes, int n_in,
                              void* d_out, int out_size) {
    const float* x    = (const float*)d_in[0];
    const int*   ei   = (const int*)d_in[1];
    const float* dx   = (const float*)d_in[2];
    const int*   dei  = (const int*)d_in[3];
    const float* W1   = (const float*)d_in[4];
    const float* as1a = (const float*)d_in[5];
    const float* ad1a = (const float*)d_in[6];
    const float* b1   = (const float*)d_in[7];
    const float* W2   = (const float*)d_in[8];
    const float* as2a = (const float*)d_in[9];
    const float* ad2a = (const float*)d_in[10];
    const float* b2   = (const float*)d_in[11];
    const float* Wg1  = (const float*)d_in[12];
    const float* bg1  = (const float*)d_in[13];
    const float* Wg2  = (const float*)d_in[14];
    const float* bg2  = (const float*)d_in[15];
    float* out = (float*)d_out;              // [NP,16] then [NDU,16]
    float* qout = out + (size_t)NP * 16;

    static cudaStream_t s1 = nullptr;
    static cudaEvent_t ev_fork = nullptr, ev_fill = nullptr, ev_done = nullptr;
    static void *p_pcnt = nullptr, *p_dcnt = nullptr, *p_cur = nullptr;
    if (!s1) {
        cudaStreamCreateWithFlags(&s1, cudaStreamNonBlocking);
        cudaEventCreateWithFlags(&ev_fork, cudaEventDisableTiming);
        cudaEventCreateWithFlags(&ev_fill, cudaEventDisableTiming);
        cudaEventCreateWithFlags(&ev_done, cudaEventDisableTiming);
        cudaGetSymbolAddress(&p_pcnt, g_pcnt);
        cudaGetSymbolAddress(&p_dcnt, g_dcnt);
        cudaGetSymbolAddress(&p_cur, g_cursor);
    }

    // zero counters via memset nodes
    cudaMemsetAsync(p_pcnt, 0, NP * sizeof(int), 0);
    cudaMemsetAsync(p_dcnt, 0, NDU * sizeof(int), 0);
    cudaMemsetAsync(p_cur, 0, 2 * sizeof(int), 0);

    cudaEventRecord(ev_fork, 0);
    cudaStreamWaitEvent(s1, ev_fork, 0);

    // stream 0: CSR build; s1: W-convert + GEMM
    k_hist<<<(EDT + 255) / 256, 256>>>(ei, dei);                            // k0
    k_wconv<<<128, 256, 0, s1>>>(W1);                                       // k1
    k_alloc<<<NPB + NDB, 1024>>>(dx);                                       // k2
    k_gemm1<<<(NP + GBM - 1) / GBM, 256, 0, s1>>>(x, as1a, ad1a);           // k3 <- profiled
    k_fill<<<(EDT + 255) / 256, 256>>>(ei, dei);                            // k4
    cudaEventRecord(ev_fill, 0);

    // s1: GAT branch
    cudaStreamWaitEvent(s1, ev_fill, 0);
    k_gat1<<<(NP * 32 + 255) / 256, 256, 0, s1>>>(b1, W2, as2a, ad2a);      // k5
    k_gat2<<<(NP * 32 + 255) / 256, 256, 0, s1>>>(W2, b2, out);             // k6

    // stream 0: dual GCN (overlaps GAT)
    k_gcn1<<<(NDU + 255) / 256, 256>>>(Wg1, bg1);                           // k7
    k_gcn2<<<(NDU + 255) / 256, 256>>>(Wg2, bg2, qout);                     // k8

    cudaEventRecord(ev_done, s1);
    cudaStreamWaitEvent(0, ev_done, 0);
}

// round 16
// speedup vs baseline: 1.3883x; 1.0333x over previous
#include <cuda_runtime.h>
#include <cuda_fp16.h>
#include <math.h>

// Problem constants
#define NP   100000      // primal nodes
#define EPn  1600000     // primal edges
#define NDU  1600000     // dual nodes
#define EDU  3200000     // dual edges
#define EPT  (EPn + NP)  // primal edges + self loops
#define EDT  (EDU + NDU) // dual edges + self loops
#define NEG_SLOPE 0.2f
#define SENT NP          // sentinel node id (weight == exactly 0)

// -------- static device scratch --------
__device__ int   g_pcnt[NP], g_poff[NP], g_pfill[NP];
__device__ int   g_dcnt[NDU], g_doff[NDU], g_dfill[NDU];
__device__ int   g_psrc[EPT + 3 * NP + 32];   // padded segments + end cushion
__device__ int   g_dsrc[EDT];
__device__ int   g_cursor[2];
__device__ float g_dinv[NDU];
__device__ uint2 g_xsv[NDU];                  // half4: dinv[n]*dx[n][0..3]
__device__ uint4 g_hv[(NP + 1) * 8];          // x @ W1, half[NP+1][64] (+sentinel)
__device__ uint4 g_heluv[(NP + 1) * 8];       // elu(GAT1 out) (+sentinel)
__device__ uint4 g_q1v[NDU];                  // dinv[n]*relu(GCN1 out)
__device__ float g_as1[(NP + 1) * 8], g_ad1[NP * 8];
__device__ float g_as2[NP + 1], g_ad2[NP];
__device__ __half g_wth[64 * 512];            // W1 transposed fp16: [n][k]

__device__ __forceinline__ float leaky(float e) { return e > 0.f ? e : NEG_SLOPE * e; }

// ---------------- CSR (dense combined; primal segments padded to x4) ----------------
__global__ void k_hist(const int* __restrict__ ei, const int* __restrict__ dei) {
    int i = blockIdx.x * blockDim.x + threadIdx.x;
    if (i < EPT) {
        int dst = (i < EPn) ? ei[EPn + i] : (i - EPn);
        atomicAdd(&g_pcnt[dst], 1);
    }
    if (i < EDT) {
        int dst = (i < EDU) ? dei[EDU + i] : (i - EDU);
        atomicAdd(&g_dcnt[dst], 1);
    }
}

__device__ __forceinline__ void alloc_body(const int* __restrict__ cnt,
                                           int* __restrict__ off,
                                           int* __restrict__ fill,
                                           int n, int curIdx, int doDinv, int doPad,
                                           int bid, const float* __restrict__ dx) {
    __shared__ int sh[1024];
    __shared__ int base;
    int t = threadIdx.x;
    int i = bid * 1024 + t;
    int v = (i < n) ? cnt[i] : 0;
    int vp = doPad ? ((v + 3) & ~3) : v;
    sh[t] = vp;
    __syncthreads();
    #pragma unroll
    for (int d = 1; d < 1024; d <<= 1) {
        int add = (t >= d) ? sh[t - d] : 0;
        __syncthreads();
        sh[t] += add;
        __syncthreads();
    }
    if (t == 1023) base = atomicAdd(&g_cursor[curIdx], sh[1023]);
    __syncthreads();
    if (i < n) {
        int o = base + sh[t] - vp;   // exclusive
        off[i] = o;
        fill[i] = o;
        if (doPad) {                 // sentinel-pad the tail of this segment
            for (int k = v; k < vp; k++) g_psrc[o + k] = SENT;
        }
        if (doDinv) {
            float di = rsqrtf((float)(v > 0 ? v : 1));
            g_dinv[i] = di;
            float4 xv = *(const float4*)&dx[(size_t)i * 4];
            __half2 a = __floats2half2_rn(di * xv.x, di * xv.y);
            __half2 b = __floats2half2_rn(di * xv.z, di * xv.w);
            g_xsv[i] = make_uint2(*(unsigned*)&a, *(unsigned*)&b);
        }
    }
}
#define NPB 98     // ceil(NP/1024)
#define NDB 1563   // ceil(NDU/1024)
__global__ void k_alloc(const float* __restrict__ dx) {
    if (blockIdx.x < NPB) alloc_body(g_pcnt, g_poff, g_pfill, NP, 0, 0, 1, blockIdx.x, dx);
    else                  alloc_body(g_dcnt, g_doff, g_dfill, NDU, 1, 1, 0, blockIdx.x - NPB, dx);
}

__global__ void k_fill(const int* __restrict__ ei, const int* __restrict__ dei) {
    int i = blockIdx.x * blockDim.x + threadIdx.x;
    if (i < EPT) {
        int src, dst;
        if (i < EPn) { src = ei[i]; dst = ei[EPn + i]; }
        else         { src = dst = i - EPn; }
        int pos = atomicAdd(&g_pfill[dst], 1);
        g_psrc[pos] = src;
    }
    if (i < EDT) {
        int src, dst;
        if (i < EDU) { src = dei[i]; dst = dei[EDU + i]; }
        else         { src = dst = i - EDU; }
        int pos = atomicAdd(&g_dfill[dst], 1);
        g_dsrc[pos] = src;
    }
}

// ---------------- dual GCN layer 1 ----------------
__global__ void k_gcn1(const float* __restrict__ Wg1, const float* __restrict__ bg1) {
    int n = blockIdx.x * blockDim.x + threadIdx.x;
    if (n >= NDU) return;
    int s = g_doff[n], cnt = g_dcnt[n];
    float4 acc = make_float4(0.f, 0.f, 0.f, 0.f);
    int e = s + cnt;
    int src = (s < e) ? g_dsrc[s] : 0;
    for (int j = s; j < e; j++) {
        int nsrc = (j + 1 < e) ? g_dsrc[j + 1] : 0;
        uint2 r = g_xsv[src];
        float2 f0 = __half22float2(*(__half2*)&r.x);
        float2 f1 = __half22float2(*(__half2*)&r.y);
        acc.x += f0.x; acc.y += f0.y; acc.z += f1.x; acc.w += f1.y;
        src = nsrc;
    }
    float di = g_dinv[n];
    acc.x *= di; acc.y *= di; acc.z *= di; acc.w *= di;
    float o[8];
    #pragma unroll
    for (int j = 0; j < 8; j++) {
        float v = __ldg(&bg1[j]);
        v = fmaf(acc.x, __ldg(&Wg1[0 * 8 + j]), v);
        v = fmaf(acc.y, __ldg(&Wg1[1 * 8 + j]), v);
        v = fmaf(acc.z, __ldg(&Wg1[2 * 8 + j]), v);
        v = fmaf(acc.w, __ldg(&Wg1[3 * 8 + j]), v);
        v = v > 0.f ? v : 0.f;     // ReLU
        o[j] = v * di;             // fold dinv[n] for layer 2
    }
    __half2 p0 = __floats2half2_rn(o[0], o[1]);
    __half2 p1 = __floats2half2_rn(o[2], o[3]);
    __half2 p2 = __floats2half2_rn(o[4], o[5]);
    __half2 p3 = __floats2half2_rn(o[6], o[7]);
    uint4 pk;
    pk.x = *(unsigned*)&p0; pk.y = *(unsigned*)&p1;
    pk.z = *(unsigned*)&p2; pk.w = *(unsigned*)&p3;
    g_q1v[n] = pk;
}

// ---------------- dual GCN layer 2 ----------------
__global__ void k_gcn2(const float* __restrict__ Wg2, const float* __restrict__ bg2,
                       float* __restrict__ qout) {
    int n = blockIdx.x * blockDim.x + threadIdx.x;
    if (n >= NDU) return;
    int s = g_doff[n], cnt = g_dcnt[n];
    float acc[8] = {};
    int e = s + cnt;
    int src = (s < e) ? g_dsrc[s] : 0;
    for (int j = s; j < e; j++) {
        int nsrc = (j + 1 < e) ? g_dsrc[j + 1] : 0;
        uint4 raw = g_q1v[src];
        float2 f0 = __half22float2(*(__half2*)&raw.x);
        float2 f1 = __half22float2(*(__half2*)&raw.y);
        float2 f2 = __half22float2(*(__half2*)&raw.z);
        float2 f3 = __half22float2(*(__half2*)&raw.w);
        acc[0] += f0.x; acc[1] += f0.y;
        acc[2] += f1.x; acc[3] += f1.y;
        acc[4] += f2.x; acc[5] += f2.y;
        acc[6] += f3.x; acc[7] += f3.y;
        src = nsrc;
    }
    float di = g_dinv[n];
    #pragma unroll
    for (int i = 0; i < 8; i++) acc[i] *= di;
    #pragma unroll
    for (int j4 = 0; j4 < 4; j4++) {
        float4 ov;
        float* op = (float*)&ov;
        #pragma unroll
        for (int t = 0; t < 4; t++) {
            int j = j4 * 4 + t;
            float v = __ldg(&bg2[j]);
            #pragma unroll
            for (int i = 0; i < 8; i++) v = fmaf(acc[i], __ldg(&Wg2[i * 16 + j]), v);
            op[t] = v;
        }
        *(float4*)&qout[(size_t)n * 16 + j4 * 4] = ov;
    }
}

// ---------------- W1 -> fp16 transposed [n][k] + sentinel init ----------------
__global__ void k_wconv(const float* __restrict__ W1) {
    int i = blockIdx.x * 256 + threadIdx.x;
    if (i < 64 * 512) {
        int n = i >> 9, k = i & 511;
        g_wth[i] = __float2half(W1[k * 64 + n]);
    }
    if (blockIdx.x == 0 && threadIdx.x < 16) {
        int t = threadIdx.x;
        if (t < 8) {
            g_as1[SENT * 8 + t] = -1e30f;
            g_hv[(size_t)SENT * 8 + t]    = make_uint4(0u, 0u, 0u, 0u);
            g_heluv[(size_t)SENT * 8 + t] = make_uint4(0u, 0u, 0u, 0u);
        }
        if (t == 8) g_as2[SENT] = -1e30f;
    }
}

// ---------------- GEMM (fp16 TC, depth-2 register pipeline, triple smem — R14) ----------------
#define GBM 128
__device__ __forceinline__ void gemm_ldx(const float* __restrict__ x, int row0,
                                         int kt, int tid, uint2* xs, uint4* wvr) {
    int k0 = kt * 32;
    #pragma unroll
    for (int i = 0; i < 4; i++) {
        int f = tid + i * 256;
        int r = f >> 3, c4 = (f & 7) << 2;
        float4 v = make_float4(0.f, 0.f, 0.f, 0.f);
        if (row0 + r < NP) v = *(const float4*)&x[(size_t)(row0 + r) * 512 + k0 + c4];
        __half2 h0 = __floats2half2_rn(v.x, v.y);
        __half2 h1 = __floats2half2_rn(v.z, v.w);
        xs[i] = make_uint2(*(unsigned*)&h0, *(unsigned*)&h1);
    }
    int n = tid >> 2, kc = (tid & 3) * 8;
    *wvr = *(const uint4*)&g_wth[n * 512 + k0 + kc];
}

__global__ __launch_bounds__(256, 2) void k_gemm1(const float* __restrict__ x,
                                                  const float* __restrict__ att_s,
                                                  const float* __restrict__ att_d) {
    __shared__ __half Xh[3][GBM][40];
    __shared__ __half Wts[3][64][40];
    int tid = threadIdx.x;
    int lane = tid & 31;
    int w = tid >> 5;
    int la3 = lane & 3, l4 = lane >> 2;
    int row0 = blockIdx.x * GBM;
    float acc[8][4] = {};
    uint2 xsA[4], xsB[4]; uint4 wA, wB;

    #define GEMM_STORE(st, xs, wv) do {                                        \
        _Pragma("unroll")                                                      \
        for (int i = 0; i < 4; i++) {                                          \
            int f = tid + i * 256;                                             \
            int r = f >> 3, c4 = (f & 7) << 2;                                 \
            *(uint2*)&Xh[st][r][c4] = (xs)[i];                                 \
        }                                                                      \
        { int n = tid >> 2, kc = (tid & 3) * 8;                                \
          *(uint2*)&Wts[st][n][kc]     = make_uint2((wv).x, (wv).y);           \
          *(uint2*)&Wts[st][n][kc + 4] = make_uint2((wv).z, (wv).w); }         \
    } while (0)

    #define GEMM_MMA(st) do {                                                  \
        _Pragma("unroll")                                                      \
        for (int ks = 0; ks < 2; ks++) {                                       \
            int kk = ks * 16 + la3 * 2;                                        \
            unsigned a[4], bfr[8][2];                                          \
            int r = w * 16 + l4;                                               \
            a[0] = *(unsigned*)&Xh[st][r][kk];                                 \
            a[1] = *(unsigned*)&Xh[st][r + 8][kk];                             \
            a[2] = *(unsigned*)&Xh[st][r][kk + 8];                             \
            a[3] = *(unsigned*)&Xh[st][r + 8][kk + 8];                         \
            _Pragma("unroll")                                                  \
            for (int n = 0; n < 8; n++) {                                      \
                int nn = n * 8 + l4;                                           \
                bfr[n][0] = *(unsigned*)&Wts[st][nn][kk];                      \
                bfr[n][1] = *(unsigned*)&Wts[st][nn][kk + 8];                  \
            }                                                                  \
            _Pragma("unroll")                                                  \
            for (int n = 0; n < 8; n++)                                        \
                asm volatile(                                                  \
                    "mma.sync.aligned.m16n8k16.row.col.f32.f16.f16.f32 "       \
                    "{%0,%1,%2,%3}, {%4,%5,%6,%7}, {%8,%9}, {%0,%1,%2,%3};\n"  \
                    : "+f"(acc[n][0]), "+f"(acc[n][1]),                        \
                      "+f"(acc[n][2]), "+f"(acc[n][3])                         \
                    : "r"(a[0]), "r"(a[1]), "r"(a[2]), "r"(a[3]),              \
                      "r"(bfr[n][0]), "r"(bfr[n][1]));                         \
        }                                                                      \
    } while (0)

    // prologue: t0 -> smem0; t1 -> regsA; t2 -> regsB
    gemm_ldx(x, row0, 0, tid, xsA, &wA);
    GEMM_STORE(0, xsA, wA);
    gemm_ldx(x, row0, 1, tid, xsA, &wA);
    gemm_ldx(x, row0, 2, tid, xsB, &wB);
    __syncthreads();

    #pragma unroll
    for (int kt = 0; kt < 16; kt += 2) {
        GEMM_MMA(kt % 3);
        if (kt + 1 < 16) {
            GEMM_STORE((kt + 1) % 3, xsA, wA);
            __syncthreads();
            if (kt + 3 < 16) gemm_ldx(x, row0, kt + 3, tid, xsA, &wA);
        }
        if (kt + 1 < 16) {
            GEMM_MMA((kt + 1) % 3);
            if (kt + 2 < 16) {
                GEMM_STORE((kt + 2) % 3, xsB, wB);
                __syncthreads();
                if (kt + 4 < 16) gemm_ldx(x, row0, kt + 4, tid, xsB, &wB);
            }
        }
    }

    // epilogue: store h fp16 + fused per-head logits
    __half* hbase = (__half*)g_hv;
    float ats[16], atd[16];
    #pragma unroll
    for (int n = 0; n < 8; n++) {
        int col = n * 8 + la3 * 2;
        ats[n * 2]     = __ldg(&att_s[col]);
        ats[n * 2 + 1] = __ldg(&att_s[col + 1]);
        atd[n * 2]     = __ldg(&att_d[col]);
        atd[n * 2 + 1] = __ldg(&att_d[col + 1]);
    }
    #pragma unroll
    for (int rh = 0; rh < 2; rh++) {
        int row = row0 + w * 16 + rh * 8 + l4;
        bool ok = (row < NP);
        #pragma unroll
        for (int n = 0; n < 8; n++) {
            float c0 = acc[n][rh * 2 + 0];
            float c1 = acc[n][rh * 2 + 1];
            if (ok) {
                __half2 hp = __floats2half2_rn(c0, c1);
                *(__half2*)&hbase[(size_t)row * 64 + n * 8 + la3 * 2] = hp;
            }
            float ss = c0 * ats[n * 2] + c1 * ats[n * 2 + 1];
            float dd = c0 * atd[n * 2] + c1 * atd[n * 2 + 1];
            ss += __shfl_xor_sync(0xffffffffu, ss, 1);
            ss += __shfl_xor_sync(0xffffffffu, ss, 2);
            dd += __shfl_xor_sync(0xffffffffu, dd, 1);
            dd += __shfl_xor_sync(0xffffffffu, dd, 2);
            if (ok && la3 == 0) {
                g_as1[(size_t)row * 8 + n] = ss;
                g_ad1[(size_t)row * 8 + n] = dd;
            }
        }
    }
}

// ---------------- GAT layer 1: guard-free pipelined loop (sentinel-padded) ----------------
__global__ __launch_bounds__(256) void k_gat1(const float* __restrict__ b1,
                                              const float* __restrict__ W2,
                                              const float* __restrict__ as2att,
                                              const float* __restrict__ ad2att) {
    __shared__ float vs[64], vd[64];
    if (threadIdx.x < 64) {
        int c = threadIdx.x;
        float s = 0.f, d = 0.f;
        #pragma unroll
        for (int j = 0; j < 16; j++) {
            float wv = __ldg(&W2[c * 16 + j]);
            s = fmaf(wv, __ldg(&as2att[j]), s);
            d = fmaf(wv, __ldg(&ad2att[j]), d);
        }
        vs[c] = s; vd[c] = d;
    }
    __syncthreads();
    int warp = (blockIdx.x * blockDim.x + threadIdx.x) >> 5;
    int lane = threadIdx.x & 31;
    if (warp >= NP) return;
    int dst = warp;
    int cnt = g_pcnt[dst];
    int cntp = (cnt + 3) & ~3;          // padded count (>= 4: self-loop guarantees cnt>=1)
    const int* bp = &g_psrc[g_poff[dst]];
    int half = lane >> 4, hl = lane & 15;
    int c0 = hl * 4;
    int head = hl >> 1;
    const uint2* hb2 = (const uint2*)g_hv;
    float adv = g_ad1[dst * 8 + head];
    float den = 0.f, a0 = 0.f, a1 = 0.f, a2 = 0.f, a3 = 0.f;

    // prologue (unguarded; over-reads land in valid padded array, clamped)
    int i0 = bp[half], i1 = bp[2 + half];
    float px0 = g_as1[i0 * 8 + head], px1 = g_as1[i1 * 8 + head];
    uint2 pr0 = hb2[(size_t)i0 * 16 + hl], pr1 = hb2[(size_t)i1 * 16 + hl];
    int n0 = bp[4 + half], n1 = bp[6 + half];
    n0 = ((unsigned)n0 > SENT) ? SENT : n0;
    n1 = ((unsigned)n1 > SENT) ? SENT : n1;
    for (int j = 0; j < cntp; j += 4) {
        int m0 = bp[j + 8 + half], m1 = bp[j + 10 + half];
        m0 = ((unsigned)m0 > SENT) ? SENT : m0;
        m1 = ((unsigned)m1 > SENT) ? SENT : m1;
        float qx0 = g_as1[n0 * 8 + head], qx1 = g_as1[n1 * 8 + head];
        uint2 qr0 = hb2[(size_t)n0 * 16 + hl], qr1 = hb2[(size_t)n1 * 16 + hl];
        float w0 = __expf(leaky(px0 + adv));
        float w1 = __expf(leaky(px1 + adv));
        float2 f00 = __half22float2(*(__half2*)&pr0.x);
        float2 f01 = __half22float2(*(__half2*)&pr0.y);
        float2 f10 = __half22float2(*(__half2*)&pr1.x);
        float2 f11 = __half22float2(*(__half2*)&pr1.y);
        den += w0 + w1;
        a0 = fmaf(w0, f00.x, a0); a1 = fmaf(w0, f00.y, a1);
        a2 = fmaf(w0, f01.x, a2); a3 = fmaf(w0, f01.y, a3);
        a0 = fmaf(w1, f10.x, a0); a1 = fmaf(w1, f10.y, a1);
        a2 = fmaf(w1, f11.x, a2); a3 = fmaf(w1, f11.y, a3);
        px0 = qx0; px1 = qx1; pr0 = qr0; pr1 = qr1;
        n0 = m0; n1 = m1;
    }
    a0 += __shfl_xor_sync(0xffffffffu, a0, 16);
    a1 += __shfl_xor_sync(0xffffffffu, a1, 16);
    a2 += __shfl_xor_sync(0xffffffffu, a2, 16);
    a3 += __shfl_xor_sync(0xffffffffu, a3, 16);
    den += __shfl_xor_sync(0xffffffffu, den, 16);
    float inv = 1.0f / (den + 1e-16f);
    float4 bv = *(const float4*)&b1[c0];
    a0 = a0 * inv + bv.x; a1 = a1 * inv + bv.y;
    a2 = a2 * inv + bv.z; a3 = a3 * inv + bv.w;
    a0 = a0 > 0.f ? a0 : (__expf(a0) - 1.f);   // ELU
    a1 = a1 > 0.f ? a1 : (__expf(a1) - 1.f);
    a2 = a2 > 0.f ? a2 : (__expf(a2) - 1.f);
    a3 = a3 > 0.f ? a3 : (__expf(a3) - 1.f);
    if (lane < 16) {
        __half2 h01 = __floats2half2_rn(a0, a1);
        __half2 h23 = __floats2half2_rn(a2, a3);
        ((uint2*)g_heluv)[(size_t)dst * 16 + hl] =
            make_uint2(*(unsigned*)&h01, *(unsigned*)&h23);
    }
    float ss = a0 * vs[c0] + a1 * vs[c0 + 1] + a2 * vs[c0 + 2] + a3 * vs[c0 + 3];
    float dd = a0 * vd[c0] + a1 * vd[c0 + 1] + a2 * vd[c0 + 2] + a3 * vd[c0 + 3];
    #pragma unroll
    for (int o = 8; o > 0; o >>= 1) {
        ss += __shfl_xor_sync(0xffffffffu, ss, o);
        dd += __shfl_xor_sync(0xffffffffu, dd, o);
    }
    if (lane == 0) { g_as2[dst] = ss; g_ad2[dst] = dd; }
}

// ---------------- GAT layer 2: guard-free pipelined loop (sentinel-padded) ----------------
__global__ __launch_bounds__(256) void k_gat2(const float* __restrict__ W2,
                                              const float* __restrict__ b2,
                                              float* __restrict__ out) {
    __shared__ float W2s[64 * 16];
    __shared__ float accs[8][64];
    for (int i = threadIdx.x; i < 64 * 16; i += blockDim.x) W2s[i] = W2[i];
    __syncthreads();
    int warp = (blockIdx.x * blockDim.x + threadIdx.x) >> 5;
    int lane = threadIdx.x & 31;
    int wip = (threadIdx.x >> 5);
    if (warp >= NP) return;
    int dst = warp;
    int cnt = g_pcnt[dst];
    int cntp = (cnt + 3) & ~3;
    const int* bp = &g_psrc[g_poff[dst]];
    int half = lane >> 4, hl = lane & 15;
    int c0 = hl * 4;
    const uint2* hb2 = (const uint2*)g_heluv;
    float adv = g_ad2[dst];
    float den = 0.f, a0 = 0.f, a1 = 0.f, a2 = 0.f, a3 = 0.f;

    int i0 = bp[half], i1 = bp[2 + half];
    float px0 = g_as2[i0], px1 = g_as2[i1];
    uint2 pr0 = hb2[(size_t)i0 * 16 + hl], pr1 = hb2[(size_t)i1 * 16 + hl];
    int n0 = bp[4 + half], n1 = bp[6 + half];
    n0 = ((unsigned)n0 > SENT) ? SENT : n0;
    n1 = ((unsigned)n1 > SENT) ? SENT : n1;
    for (int j = 0; j < cntp; j += 4) {
        int m0 = bp[j + 8 + half], m1 = bp[j + 10 + half];
        m0 = ((unsigned)m0 > SENT) ? SENT : m0;
        m1 = ((unsigned)m1 > SENT) ? SENT : m1;
        float qx0 = g_as2[n0], qx1 = g_as2[n1];
        uint2 qr0 = hb2[(size_t)n0 * 16 + hl], qr1 = hb2[(size_t)n1 * 16 + hl];
        float w0 = __expf(leaky(px0 + adv));
        float w1 = __expf(leaky(px1 + adv));
        float2 f00 = __half22float2(*(__half2*)&pr0.x);
        float2 f01 = __half22float2(*(__half2*)&pr0.y);
        float2 f10 = __half22float2(*(__half2*)&pr1.x);
        float2 f11 = __half22float2(*(__half2*)&pr1.y);
        den += w0 + w1;
        a0 = fmaf(w0, f00.x, a0); a1 = fmaf(w0, f00.y, a1);
        a2 = fmaf(w0, f01.x, a2); a3 = fmaf(w0, f01.y, a3);
        a0 = fmaf(w1, f10.x, a0); a1 = fmaf(w1, f10.y, a1);
        a2 = fmaf(w1, f11.x, a2); a3 = fmaf(w1, f11.y, a3);
        px0 = qx0; px1 = qx1; pr0 = qr0; pr1 = qr1;
        n0 = m0; n1 = m1;
    }
    a0 += __shfl_xor_sync(0xffffffffu, a0, 16);
    a1 += __shfl_xor_sync(0xffffffffu, a1, 16);
    a2 += __shfl_xor_sync(0xffffffffu, a2, 16);
    a3 += __shfl_xor_sync(0xffffffffu, a3, 16);
    den += __shfl_xor_sync(0xffffffffu, den, 16);
    float inv = 1.0f / (den + 1e-16f);
    if (lane < 16) {
        accs[wip][c0]     = a0 * inv;
        accs[wip][c0 + 1] = a1 * inv;
        accs[wip][c0 + 2] = a2 * inv;
        accs[wip][c0 + 3] = a3 * inv;
    }
    __syncwarp();
    if (lane < 16) {
        float o = __ldg(&b2[lane]);
        #pragma unroll
        for (int c = 0; c < 64; c++) o = fmaf(accs[wip][c], W2s[c * 16 + lane], o);
        out[dst * 16 + lane] = o;
    }
}

// ---------------- launcher: forked-stream graph ----------------
extern "C" void kernel_launch(void* const* d_in, const int* in_sizes, int n_in,
                              void* d_out, int out_size) {
    const float* x    = (const float*)d_in[0];
    const int*   ei   = (const int*)d_in[1];
    const float* dx   = (const float*)d_in[2];
    const int*   dei  = (const int*)d_in[3];
    const float* W1   = (const float*)d_in[4];
    const float* as1a = (const float*)d_in[5];
    const float* ad1a = (const float*)d_in[6];
    const float* b1   = (const float*)d_in[7];
    const float* W2   = (const float*)d_in[8];
    const float* as2a = (const float*)d_in[9];
    const float* ad2a = (const float*)d_in[10];
    const float* b2   = (const float*)d_in[11];
    const float* Wg1  = (const float*)d_in[12];
    const float* bg1  = (const float*)d_in[13];
    const float* Wg2  = (const float*)d_in[14];
    const float* bg2  = (const float*)d_in[15];
    float* out = (float*)d_out;              // [NP,16] then [NDU,16]
    float* qout = out + (size_t)NP * 16;

    static cudaStream_t s1 = nullptr;
    static cudaEvent_t ev_fork = nullptr, ev_fill = nullptr, ev_done = nullptr;
    static void *p_pcnt = nullptr, *p_dcnt = nullptr, *p_cur = nullptr;
    if (!s1) {
        cudaStreamCreateWithFlags(&s1, cudaStreamNonBlocking);
        cudaEventCreateWithFlags(&ev_fork, cudaEventDisableTiming);
        cudaEventCreateWithFlags(&ev_fill, cudaEventDisableTiming);
        cudaEventCreateWithFlags(&ev_done, cudaEventDisableTiming);
        cudaGetSymbolAddress(&p_pcnt, g_pcnt);
        cudaGetSymbolAddress(&p_dcnt, g_dcnt);
        cudaGetSymbolAddress(&p_cur, g_cursor);
    }

    // zero counters via memset nodes
    cudaMemsetAsync(p_pcnt, 0, NP * sizeof(int), 0);
    cudaMemsetAsync(p_dcnt, 0, NDU * sizeof(int), 0);
    cudaMemsetAsync(p_cur, 0, 2 * sizeof(int), 0);

    cudaEventRecord(ev_fork, 0);
    cudaStreamWaitEvent(s1, ev_fork, 0);

    // stream 0: CSR build; s1: W-convert(+sentinels) + GEMM
    k_hist<<<(EDT + 255) / 256, 256>>>(ei, dei);                            // k0
    k_wconv<<<128, 256, 0, s1>>>(W1);                                       // k1
    k_alloc<<<NPB + NDB, 1024>>>(dx);                                       // k2
    k_gemm1<<<(NP + GBM - 1) / GBM, 256, 0, s1>>>(x, as1a, ad1a);           // k3 <- profiled
    k_fill<<<(EDT + 255) / 256, 256>>>(ei, dei);                            // k4
    cudaEventRecord(ev_fill, 0);

    // s1: GAT branch
    cudaStreamWaitEvent(s1, ev_fill, 0);
    k_gat1<<<(NP * 32 + 255) / 256, 256, 0, s1>>>(b1, W2, as2a, ad2a);      // k5
    k_gat2<<<(NP * 32 + 255) / 256, 256, 0, s1>>>(W2, b2, out);             // k6

    // stream 0: dual GCN (overlaps GAT)
    k_gcn1<<<(NDU + 255) / 256, 256>>>(Wg1, bg1);                           // k7
    k_gcn2<<<(NDU + 255) / 256, 256>>>(Wg2, bg2, qout);                     // k8

    cudaEventRecord(ev_done, s1);
    cudaStreamWaitEvent(0, ev_done, 0);
}